// round 14
// baseline (speedup 1.0000x reference)
#include <cuda_runtime.h>
#include <cuda_bf16.h>
#include <cstdint>
#include <math.h>

#define Lc 128
#define Bc 32
#define Tc 64
#define TDc 63
#define Ec 512
#define Hc 512
#define Ac 512
#define Vc 32000
#define G3 1536
#define MBc (TDc*Bc)   // 2016
#define MPAD 2048

typedef unsigned long long ull;

// ---------------- scratch ----------------
__device__ float d_emb   [Lc*Bc*Ec];
__device__ float d_decemb[MBc*Ec];
__device__ float d_gi    [Lc*Bc*2*G3];
__device__ float d_y0    [Lc*Bc*2*Hc];
__device__ float d_y1    [Lc*Bc*2*Hc];
__device__ float d_eo    [Lc*Bc*Hc];
__device__ float d_eq    [Lc*Bc*Ac];
__device__ float d_dpre  [MPAD*G3];
__device__ float d_h0b   [2*Bc*Hc];
__device__ float d_h1b   [2*Bc*Hc];
__device__ float d_ctxb  [2*Bc*Hc];
__device__ float d_qb    [Bc*Ac];
__device__ float d_feat  [MBc*2*Hc];
__device__ unsigned d_bars[4];
// bf16 split operand buffers
__device__ __nv_bfloat16 d_Ah[4096*1024];
__device__ __nv_bfloat16 d_Al[4096*1024];
__device__ __nv_bfloat16 d_Wh[3072*1024];
__device__ __nv_bfloat16 d_Wl[3072*1024];
__device__ __nv_bfloat16 d_Bh[(size_t)Vc*1024];
__device__ __nv_bfloat16 d_Bl[(size_t)Vc*1024];

// ---------------- packed fp32x2 FMA (Blackwell sm_100+ baseline PTX) ----------------
#define FMA2(acc, h, w) \
    asm("fma.rn.f32x2 %0, %1, %2, %0;" : "+l"(acc) : "l"(h), "l"(w))
__device__ __forceinline__ float red2(ull a) {
    return __uint_as_float((unsigned)a) + __uint_as_float((unsigned)(a >> 32));
}

// ---------------- grid barrier (all blocks co-resident: grid <= 148) ---------------
__device__ __forceinline__ void gbar(unsigned* cnt, unsigned target) {
    __threadfence();
    __syncthreads();
    if (threadIdx.x == 0) {
        unsigned v;
        asm volatile("red.release.gpu.global.add.u32 [%0], 1;" :: "l"(cnt) : "memory");
        do {
            asm volatile("ld.acquire.gpu.global.u32 %0, [%1];" : "=r"(v) : "l"(cnt) : "memory");
        } while (v < target);
    }
    __syncthreads();
}

// ---------------- embedding gathers ----------------
__global__ void gather_rows(const int* __restrict__ tok, const float* __restrict__ tab,
                            float* __restrict__ out, int mode)
{
    int row = blockIdx.x;
    int idx;
    if (mode == 0) idx = tok[row];
    else { int t = row >> 5, b = row & 31; idx = tok[b*Tc + t]; }
    const float4* src = (const float4*)(tab + (size_t)idx * Ec);
    float4* dst = (float4*)(out + (size_t)row * Ec);
    dst[threadIdx.x] = src[threadIdx.x];
}

// ---------------- fp32 -> split bf16 ----------------
__global__ void conv_split(const float* __restrict__ in, __nv_bfloat16* __restrict__ hi,
                           __nv_bfloat16* __restrict__ lo, long n_valid, long n_total)
{
    long i = (long)blockIdx.x * blockDim.x + threadIdx.x;
    if (i >= n_total) return;
    float v = (i < n_valid) ? in[i] : 0.f;
    __nv_bfloat16 h = __float2bfloat16(v);
    hi[i] = h;
    lo[i] = __float2bfloat16(v - __bfloat162float(h));
}
__global__ void conv_split2d(const float* __restrict__ in, int ld, int rows, int cols,
                             __nv_bfloat16* __restrict__ hi, __nv_bfloat16* __restrict__ lo)
{
    long i = (long)blockIdx.x * blockDim.x + threadIdx.x;
    if (i >= (long)rows * cols) return;
    int r = (int)(i / cols), c = (int)(i % cols);
    float v = in[(size_t)r * ld + c];
    __nv_bfloat16 h = __float2bfloat16(v);
    hi[i] = h;
    lo[i] = __float2bfloat16(v - __bfloat162float(h));
}

// =============== generic split-bf16 tensor GEMM; grid: x = M-tiles (fast), y = N-tiles ========
#define F_RELU  1
#define F_REMAP 2
#define F_SPLIT 4
#define SLDA 40
#define TILEB (128*SLDA*2)
#define STAGEB (4*TILEB)
#define GEMM_SMEM (2*STAGEB)

__device__ __forceinline__ uint32_t smem_u32(const void* p) {
    uint32_t a;
    asm("{ .reg .u64 t; cvta.to.shared.u64 t, %1; cvt.u32.u64 %0, t; }" : "=r"(a) : "l"(p));
    return a;
}
__device__ __forceinline__ void ldm4(uint32_t& r0, uint32_t& r1, uint32_t& r2, uint32_t& r3, uint32_t a) {
    asm volatile("ldmatrix.sync.aligned.m8n8.x4.shared.b16 {%0,%1,%2,%3}, [%4];"
                 : "=r"(r0), "=r"(r1), "=r"(r2), "=r"(r3) : "r"(a));
}
__device__ __forceinline__ void mma16816(float* c, const uint32_t* a, const uint32_t* b) {
    asm volatile("mma.sync.aligned.m16n8k16.row.col.f32.bf16.bf16.f32 "
                 "{%0,%1,%2,%3},{%4,%5,%6,%7},{%8,%9},{%0,%1,%2,%3};"
                 : "+f"(c[0]), "+f"(c[1]), "+f"(c[2]), "+f"(c[3])
                 : "r"(a[0]), "r"(a[1]), "r"(a[2]), "r"(a[3]), "r"(b[0]), "r"(b[1]));
}
#define CP16(dst, src) asm volatile("cp.async.cg.shared.global [%0], [%1], 16;" :: "r"(dst), "l"(src))
#define CP_COMMIT()    asm volatile("cp.async.commit_group;" ::: "memory")
#define CP_WAIT1()     asm volatile("cp.async.wait_group 1;" ::: "memory")

__global__ __launch_bounds__(256) void gemm_bf16(
    int K,
    const __nv_bfloat16* __restrict__ Ah, const __nv_bfloat16* __restrict__ Al,
    const __nv_bfloat16* __restrict__ Bh, const __nv_bfloat16* __restrict__ Bl,
    const float* __restrict__ bias,
    float* __restrict__ Cf, __nv_bfloat16* __restrict__ Chi, __nv_bfloat16* __restrict__ Clo,
    int ldc, int flags)
{
    extern __shared__ char smem[];
    const uint32_t smem_base = smem_u32(smem);
    const int tid = threadIdx.x, wid = tid >> 5, lane = tid & 31;
    const int mBase = blockIdx.x * 128;   // M fastest: better B reuse in L2 across a wave
    const int nBase = blockIdx.y * 128;
    const int warpM = (wid & 1) * 64;
    const int warpN = (wid >> 1) * 32;

    const __nv_bfloat16* g[4] = {
        Ah + (size_t)mBase * K, Al + (size_t)mBase * K,
        Bh + (size_t)nBase * K, Bl + (size_t)nBase * K };

    const int lRow0 = tid >> 2, lSc0 = (tid & 3);
    const int lRow1 = (tid + 256) >> 2, lSc1 = ((tid + 256) & 3);

    auto prefetch = [&](int st, int kc) {
        #pragma unroll
        for (int op = 0; op < 4; op++) {
            uint32_t sb = smem_base + st * STAGEB + op * TILEB;
            CP16(sb + (uint32_t)(lRow0 * SLDA + lSc0 * 8) * 2, g[op] + (size_t)lRow0 * K + kc + lSc0 * 8);
            CP16(sb + (uint32_t)(lRow1 * SLDA + lSc1 * 8) * 2, g[op] + (size_t)lRow1 * K + kc + lSc1 * 8);
        }
    };

    float acc[4][4][4];
    #pragma unroll
    for (int i = 0; i < 4; i++)
        #pragma unroll
        for (int j = 0; j < 4; j++)
            #pragma unroll
            for (int e = 0; e < 4; e++) acc[i][j][e] = 0.f;

    const int aRow = (lane & 15), aK = (lane >> 4) * 8;
    const int bRow = ((lane >> 4) << 3) + (lane & 7), bK = ((lane >> 3) & 1) * 8;

    const int nch = K >> 5;
    prefetch(0, 0);
    CP_COMMIT();

    for (int c = 0; c < nch; c++) {
        if (c + 1 < nch) prefetch((c + 1) & 1, (c + 1) << 5);
        CP_COMMIT();
        CP_WAIT1();
        __syncthreads();

        const uint32_t stb = smem_base + (c & 1) * STAGEB;
        const uint32_t bAh = stb, bAl = stb + TILEB, bBh = stb + 2*TILEB, bBl = stb + 3*TILEB;

        #pragma unroll
        for (int ks = 0; ks < 2; ks++) {
            const int kb = ks * 16;
            uint32_t fbh[4][2], fbl[4][2];
            #pragma unroll
            for (int nt = 0; nt < 2; nt++) {
                uint32_t off = ((uint32_t)(warpN + nt * 16 + bRow) * SLDA + kb + bK) * 2;
                ldm4(fbh[nt*2][0], fbh[nt*2][1], fbh[nt*2+1][0], fbh[nt*2+1][1], bBh + off);
                ldm4(fbl[nt*2][0], fbl[nt*2][1], fbl[nt*2+1][0], fbl[nt*2+1][1], bBl + off);
            }
            #pragma unroll
            for (int mi = 0; mi < 4; mi++) {
                uint32_t fah[4], fal[4];
                uint32_t off = ((uint32_t)(warpM + mi * 16 + aRow) * SLDA + kb + aK) * 2;
                ldm4(fah[0], fah[1], fah[2], fah[3], bAh + off);
                ldm4(fal[0], fal[1], fal[2], fal[3], bAl + off);
                #pragma unroll
                for (int ni = 0; ni < 4; ni++) {
                    mma16816(acc[mi][ni], fah, fbh[ni]);
                    mma16816(acc[mi][ni], fah, fbl[ni]);
                    mma16816(acc[mi][ni], fal, fbh[ni]);
                }
            }
        }
        __syncthreads();
    }

    const int mLane = lane >> 2;
    const int nLane = (lane & 3) * 2;
    #pragma unroll
    for (int mi = 0; mi < 4; mi++) {
        #pragma unroll
        for (int half = 0; half < 2; half++) {
            int m = mBase + warpM + mi * 16 + mLane + half * 8;
            int orow = m;
            if (flags & F_REMAP) {
                if (m >= MBc) continue;
                orow = (m & 31) * TDc + (m >> 5);
            }
            #pragma unroll
            for (int ni = 0; ni < 4; ni++) {
                int n = nBase + warpN + ni * 8 + nLane;
                float vx = acc[mi][ni][half * 2 + 0] + bias[n];
                float vy = acc[mi][ni][half * 2 + 1] + bias[n + 1];
                if (flags & F_RELU) { vx = fmaxf(vx, 0.f); vy = fmaxf(vy, 0.f); }
                if (flags & F_SPLIT) {
                    size_t o = (size_t)orow * ldc + n;
                    __nv_bfloat16 hx = __float2bfloat16(vx), hy = __float2bfloat16(vy);
                    Chi[o] = hx; Chi[o+1] = hy;
                    Clo[o]   = __float2bfloat16(vx - __bfloat162float(hx));
                    Clo[o+1] = __float2bfloat16(vy - __bfloat162float(hy));
                } else {
                    *(float2*)(Cf + (size_t)orow * ldc + n) = make_float2(vx, vy);
                }
            }
        }
    }
}

// ---------------- recurrent helpers (f32x2, stride-130 h tile) ----------------
#define HS 130   // floats per h row in smem: LDS.64 bank = (2r+k) mod 32 -> conflict-free

__device__ __forceinline__ void gate3f2(
    const float* hrow, const float* pr, const float* pz, const float* pn,
    ull& a0, ull& a1, ull& a2)
{
    #pragma unroll 8
    for (int k = 0; k < 128; k += 4) {
        ull h01 = *(const ull*)(hrow + k);
        ull h23 = *(const ull*)(hrow + k + 2);
        FMA2(a0, h01, *(const ull*)(pr + k)); FMA2(a0, h23, *(const ull*)(pr + k + 2));
        FMA2(a1, h01, *(const ull*)(pz + k)); FMA2(a1, h23, *(const ull*)(pz + k + 2));
        FMA2(a2, h01, *(const ull*)(pn + k)); FMA2(a2, h23, *(const ull*)(pn + k + 2));
    }
}
// stage 32 x 128 chunk from [32 x Hc] global into hs (stride HS), float2 granules
__device__ __forceinline__ void stage_tile(float* hs, const float* src, int kc, int nthr, int tid) {
    for (int i = tid; i < 2048; i += nthr) {
        int r = i >> 6, kk = (i & 63) << 1;
        *(float2*)&hs[r*HS + kk] = *(const float2*)&src[(size_t)r*Hc + kc + kk];
    }
}

// =============== persistent encoder GRU layer: 128 blocks, 128 steps internal ===============
#define ENC_SMEM (49152 + 32*HS*4)
__global__ __launch_bounds__(256) void enc_gru_persist(
    const float* __restrict__ gi, const float* __restrict__ WhhBase,
    const float* __restrict__ bhhBase, float* __restrict__ y, unsigned* bar)
{
    extern __shared__ char sm[];
    float* wsm = (float*)sm;                            // [3][8][512]
    float* hs  = (float*)(sm + 49152);                  // [32][HS]
    const int tid = threadIdx.x, wid = tid >> 5, row = tid & 31;
    const int dir = blockIdx.x >> 6;
    const int jb  = blockIdx.x & 63;
    const int j   = jb * 8 + wid;
    const int dcol = dir * Hc;
    const float* Whh = WhhBase + (size_t)dir * G3 * Hc;
    const float* bhh = bhhBase + dir * G3;

    for (int i = tid; i < 3*8*512; i += 256) {
        int g = i >> 12, rem = i & 4095, w = rem >> 9, k = rem & 511;
        wsm[i] = Whh[(size_t)(g*Hc + jb*8 + w)*Hc + k];
    }
    const float b0 = bhh[j], b1 = bhh[Hc + j], b2 = bhh[2*Hc + j];
    __syncthreads();

    for (int s = 0; s < Lc; s++) {
        const int te = dir ? (Lc - 1 - s) : s;
        const int tprev = dir ? (te + 1) : (te - 1);
        const bool first = (s == 0);
        ull ar = 0ull, az = 0ull, an = 0ull;
        for (int kc = 0; kc < Hc; kc += 128) {
            for (int i = tid; i < 2048; i += 256) {
                int r = i >> 6, kk = (i & 63) << 1;
                float2 v = make_float2(0.f, 0.f);
                if (!first) v = *(const float2*)&y[((size_t)tprev*Bc + r)*(2*Hc) + dcol + kc + kk];
                *(float2*)&hs[r*HS + kk] = v;
            }
            __syncthreads();
            gate3f2(hs + row*HS, wsm + wid*512 + kc, wsm + 4096 + wid*512 + kc,
                    wsm + 8192 + wid*512 + kc, ar, az, an);
            __syncthreads();
        }
        const float* gp = gi + ((size_t)te*Bc + row) * (2*G3) + dir * G3;
        float rg = 1.f / (1.f + __expf(-(gp[j]      + red2(ar) + b0)));
        float zg = 1.f / (1.f + __expf(-(gp[Hc + j] + red2(az) + b1)));
        float ng = tanhf(gp[2*Hc + j] + rg * (red2(an) + b2));
        float hp = first ? 0.f : y[((size_t)tprev*Bc + row)*(2*Hc) + dcol + j];
        y[((size_t)te*Bc + row)*(2*Hc) + dcol + j] = (1.f - zg)*ng + zg*hp;
        if (s < Lc - 1) gbar(bar, 128u * (unsigned)(s + 1));
    }
}

// ---------------- enc_out = y1[:, :H] + y1[:, H:] ----------------
__global__ void combine_enc(const float* __restrict__ y1, float* __restrict__ eo)
{
    int i = blockIdx.x;
    int h = threadIdx.x * 4;
    float4 a = *(const float4*)&y1[(size_t)i*2*Hc + h];
    float4 b = *(const float4*)&y1[(size_t)i*2*Hc + Hc + h];
    *(float4*)&eo[(size_t)i*Hc + h] = make_float4(a.x+b.x, a.y+b.y, a.z+b.z, a.w+b.w);
}

// =============== persistent decoder: 128 blocks x 128 thr, 63 steps x 4 phases ===============
#define DEC_SMEM (4*24576 + 8192 + 32*HS*4 + (512+128+4)*4)
__global__ __launch_bounds__(128) void dec_persist(
    const float* __restrict__ dWih0, const float* __restrict__ dWhh0,
    const float* __restrict__ bhh0,
    const float* __restrict__ dWih1, const float* __restrict__ dWhh1,
    const float* __restrict__ bih1, const float* __restrict__ bhh1,
    const float* __restrict__ Wd, const float* __restrict__ bd,
    const float* __restrict__ dpre,
    const float* __restrict__ encq, const float* __restrict__ encout,
    float* __restrict__ h0b, float* __restrict__ h1b, float* __restrict__ ctxb,
    float* __restrict__ qb, float* __restrict__ feat, unsigned* bar)
{
    extern __shared__ char sm[];
    float* wx0 = (float*)sm;                 // each [3][4][512] = 6144 floats
    float* wh0 = wx0 + 6144;
    float* wx1 = wh0 + 6144;
    float* wh1 = wx1 + 6144;
    float* wd  = wh1 + 6144;                 // [4][512]
    float* hs  = wd + 2048;                  // [32][HS]
    float* qs   = hs + 32*HS;                // 512
    float* es   = qs + 512;                  // 128
    float* ssum = es + 128;                  // 4

    const int tid = threadIdx.x, w = tid >> 5, lane = tid & 31, row = lane;
    const int blk = blockIdx.x;
    const int j = blk * 4 + w;

    for (int i = tid; i < 6144; i += 128) {
        int g = i / 2048, rem = i - g*2048, ww = rem >> 9, k = rem & 511;
        int r0 = g*Hc + blk*4 + ww;
        wx0[i] = dWih0[(size_t)r0*(Ec + Hc) + Ec + k];
        wh0[i] = dWhh0[(size_t)r0*Hc + k];
        wx1[i] = dWih1[(size_t)r0*Hc + k];
        wh1[i] = dWhh1[(size_t)r0*Hc + k];
    }
    for (int i = tid; i < 2048; i += 128)
        wd[i] = Wd[(size_t)(blk*4 + (i >> 9))*Hc + (i & 511)];
    const float bh0r = bhh0[j], bh0z = bhh0[Hc+j], bh0n = bhh0[2*Hc+j];
    const float bi1r = bih1[j], bi1z = bih1[Hc+j], bi1n = bih1[2*Hc+j];
    const float bh1r = bhh1[j], bh1z = bhh1[Hc+j], bh1n = bhh1[2*Hc+j];
    const float bdj = bd[j];
    __syncthreads();

    unsigned bi = 0;
    for (int t = 0; t < TDc; t++) {
        const int r = t & 1, wix = 1 - r;
        const float* ctxp = ctxb + (size_t)r*Bc*Hc;
        const float* h0p  = h0b  + (size_t)r*Bc*Hc;
        float*       h0n  = h0b  + (size_t)wix*Bc*Hc;
        const float* h1p  = h1b  + (size_t)r*Bc*Hc;
        float*       h1n  = h1b  + (size_t)wix*Bc*Hc;

        // ---- phase 1: cell0 (x=ctx, h=h0) ----
        {
            ull air=0ull, aiz=0ull, ain=0ull, ahr=0ull, ahz=0ull, ahn=0ull;
            for (int kc = 0; kc < Hc; kc += 128) {
                stage_tile(hs, ctxp, kc, 128, tid);
                __syncthreads();
                gate3f2(hs + row*HS, wx0 + w*512 + kc, wx0 + 2048 + w*512 + kc,
                        wx0 + 4096 + w*512 + kc, air, aiz, ain);
                __syncthreads();
            }
            for (int kc = 0; kc < Hc; kc += 128) {
                stage_tile(hs, h0p, kc, 128, tid);
                __syncthreads();
                gate3f2(hs + row*HS, wh0 + w*512 + kc, wh0 + 2048 + w*512 + kc,
                        wh0 + 4096 + w*512 + kc, ahr, ahz, ahn);
                __syncthreads();
            }
            const float* pre = dpre + ((size_t)t*Bc + row)*G3;
            float rg = 1.f / (1.f + __expf(-(red2(air) + pre[j]      + red2(ahr) + bh0r)));
            float zg = 1.f / (1.f + __expf(-(red2(aiz) + pre[Hc+j]   + red2(ahz) + bh0z)));
            float ng = tanhf(red2(ain) + pre[2*Hc+j] + rg * (red2(ahn) + bh0n));
            h0n[(size_t)row*Hc + j] = (1.f - zg)*ng + zg*h0p[(size_t)row*Hc + j];
        }
        gbar(bar, 128u * (++bi));

        // ---- phase 2: cell1 (x=h0n, h=h1) ----
        {
            ull air=0ull, aiz=0ull, ain=0ull, ahr=0ull, ahz=0ull, ahn=0ull;
            for (int kc = 0; kc < Hc; kc += 128) {
                stage_tile(hs, h0n, kc, 128, tid);
                __syncthreads();
                gate3f2(hs + row*HS, wx1 + w*512 + kc, wx1 + 2048 + w*512 + kc,
                        wx1 + 4096 + w*512 + kc, air, aiz, ain);
                __syncthreads();
            }
            for (int kc = 0; kc < Hc; kc += 128) {
                stage_tile(hs, h1p, kc, 128, tid);
                __syncthreads();
                gate3f2(hs + row*HS, wh1 + w*512 + kc, wh1 + 2048 + w*512 + kc,
                        wh1 + 4096 + w*512 + kc, ahr, ahz, ahn);
                __syncthreads();
            }
            float rg = 1.f / (1.f + __expf(-(red2(air) + bi1r + red2(ahr) + bh1r)));
            float zg = 1.f / (1.f + __expf(-(red2(aiz) + bi1z + red2(ahz) + bh1z)));
            float ng = tanhf(red2(ain) + bi1n + rg * (red2(ahn) + bh1n));
            h1n[(size_t)row*Hc + j] = (1.f - zg)*ng + zg*h1p[(size_t)row*Hc + j];
        }
        gbar(bar, 128u * (++bi));

        // ---- phase 3: q = h1n @ Wd^T + bd ----
        {
            ull acc = 0ull;
            for (int kc = 0; kc < Hc; kc += 128) {
                stage_tile(hs, h1n, kc, 128, tid);
                __syncthreads();
                const float* wj = wd + w*512 + kc;
                const float* hrow = hs + row*HS;
                #pragma unroll 8
                for (int k = 0; k < 128; k += 4) {
                    FMA2(acc, *(const ull*)(hrow + k),     *(const ull*)(wj + k));
                    FMA2(acc, *(const ull*)(hrow + k + 2), *(const ull*)(wj + k + 2));
                }
                __syncthreads();
            }
            qb[(size_t)row*Hc + j] = red2(acc) + bdj;
        }
        gbar(bar, 128u * (++bi));

        // ---- phase 4: attention + feat (blocks 0..31, b = blk) ----
        if (blk < 32) {
            const int b = blk;
            qs[tid]       = qb[(size_t)b*Hc + tid];
            qs[tid + 128] = qb[(size_t)b*Hc + tid + 128];
            qs[tid + 256] = qb[(size_t)b*Hc + tid + 256];
            qs[tid + 384] = qb[(size_t)b*Hc + tid + 384];
            __syncthreads();
            for (int l = w; l < Lc; l += 4) {
                const float* eqr = encq + ((size_t)l*Bc + b) * Ac;
                float s = 0.f;
                #pragma unroll
                for (int qk = 0; qk < 4; qk++) {
                    int k = qk*128 + lane*4;
                    float4 a = *(const float4*)&eqr[k];
                    float4 c = *(const float4*)&qs[k];
                    s += a.x*c.x + a.y*c.y + a.z*c.z + a.w*c.w;
                }
                #pragma unroll
                for (int off = 16; off; off >>= 1) s += __shfl_xor_sync(0xffffffffu, s, off);
                if (lane == 0) es[l] = __expf(tanhf(s));
            }
            __syncthreads();
            {
                float v = es[tid];
                #pragma unroll
                for (int off = 16; off; off >>= 1) v += __shfl_xor_sync(0xffffffffu, v, off);
                if (lane == 0) ssum[w] = v;
            }
            __syncthreads();
            float inv = 1.f / (ssum[0] + ssum[1] + ssum[2] + ssum[3]);
            float a0=0.f, a1=0.f, a2=0.f, a3=0.f;
            for (int l = 0; l < Lc; l++) {
                float wl = es[l];
                const float* eor = encout + ((size_t)l*Bc + b) * Hc;
                a0 += wl*eor[tid]; a1 += wl*eor[tid+128]; a2 += wl*eor[tid+256]; a3 += wl*eor[tid+384];
            }
            a0 *= inv; a1 *= inv; a2 *= inv; a3 *= inv;
            float* cx = ctxb + (size_t)wix*Bc*Hc + (size_t)b*Hc;
            cx[tid]=a0; cx[tid+128]=a1; cx[tid+256]=a2; cx[tid+384]=a3;
            float* fp = feat + ((size_t)t*Bc + b) * 2*Hc;
            const float* h1r = h1n + (size_t)b*Hc;
            fp[tid]=h1r[tid]; fp[tid+128]=h1r[tid+128]; fp[tid+256]=h1r[tid+256]; fp[tid+384]=h1r[tid+384];
            fp[Hc+tid]=a0; fp[Hc+tid+128]=a1; fp[Hc+tid+256]=a2; fp[Hc+tid+384]=a3;
            __syncthreads();
        }
        ++bi;
        if (t < TDc - 1) gbar(bar, 128u * bi);
    }
}

// ================================================================================
extern "C" void kernel_launch(void* const* d_in, const int* in_sizes, int n_in,
                              void* d_out, int out_size)
{
    const int*   src_tokens = (const int*)  d_in[0];
    const int*   trgt_seq   = (const int*)  d_in[1];
    const float* enc_embed  = (const float*)d_in[3];
    const float* enc_Wih0   = (const float*)d_in[4];
    const float* enc_Whh0   = (const float*)d_in[5];
    const float* enc_bih0   = (const float*)d_in[6];
    const float* enc_bhh0   = (const float*)d_in[7];
    const float* enc_Wih1   = (const float*)d_in[8];
    const float* enc_Whh1   = (const float*)d_in[9];
    const float* enc_bih1   = (const float*)d_in[10];
    const float* enc_bhh1   = (const float*)d_in[11];
    const float* dec_embed  = (const float*)d_in[12];
    const float* dec_Wih0   = (const float*)d_in[13];
    const float* dec_Whh0   = (const float*)d_in[14];
    const float* dec_bih0   = (const float*)d_in[15];
    const float* dec_bhh0   = (const float*)d_in[16];
    const float* dec_Wih1   = (const float*)d_in[17];
    const float* dec_Whh1   = (const float*)d_in[18];
    const float* dec_bih1   = (const float*)d_in[19];
    const float* dec_bhh1   = (const float*)d_in[20];
    const float* attn_We    = (const float*)d_in[21];
    const float* attn_be    = (const float*)d_in[22];
    const float* attn_Wd    = (const float*)d_in[23];
    const float* attn_bd    = (const float*)d_in[24];
    const float* mlp_W1     = (const float*)d_in[25];
    const float* mlp_b1     = (const float*)d_in[26];
    const float* mlp_W2     = (const float*)d_in[27];
    const float* mlp_b2     = (const float*)d_in[28];

    float *emb, *decemb, *gi, *y0, *y1, *eo, *eq, *dpre, *h0b, *h1b, *ctxb, *qb, *feat;
    unsigned* bars;
    __nv_bfloat16 *Ah, *Al, *Wh, *Wl, *Bh, *Bl;
    cudaGetSymbolAddress((void**)&emb,    d_emb);
    cudaGetSymbolAddress((void**)&decemb, d_decemb);
    cudaGetSymbolAddress((void**)&gi,     d_gi);
    cudaGetSymbolAddress((void**)&y0,     d_y0);
    cudaGetSymbolAddress((void**)&y1,     d_y1);
    cudaGetSymbolAddress((void**)&eo,     d_eo);
    cudaGetSymbolAddress((void**)&eq,     d_eq);
    cudaGetSymbolAddress((void**)&dpre,   d_dpre);
    cudaGetSymbolAddress((void**)&h0b,    d_h0b);
    cudaGetSymbolAddress((void**)&h1b,    d_h1b);
    cudaGetSymbolAddress((void**)&ctxb,   d_ctxb);
    cudaGetSymbolAddress((void**)&qb,     d_qb);
    cudaGetSymbolAddress((void**)&feat,   d_feat);
    cudaGetSymbolAddress((void**)&bars,   d_bars);
    cudaGetSymbolAddress((void**)&Ah,     d_Ah);
    cudaGetSymbolAddress((void**)&Al,     d_Al);
    cudaGetSymbolAddress((void**)&Wh,     d_Wh);
    cudaGetSymbolAddress((void**)&Wl,     d_Wl);
    cudaGetSymbolAddress((void**)&Bh,     d_Bh);
    cudaGetSymbolAddress((void**)&Bl,     d_Bl);

    cudaFuncSetAttribute(gemm_bf16,       cudaFuncAttributeMaxDynamicSharedMemorySize, GEMM_SMEM);
    cudaFuncSetAttribute(enc_gru_persist, cudaFuncAttributeMaxDynamicSharedMemorySize, ENC_SMEM);
    cudaFuncSetAttribute(dec_persist,     cudaFuncAttributeMaxDynamicSharedMemorySize, DEC_SMEM);

    cudaMemsetAsync(bars, 0, 4*sizeof(unsigned));
    cudaMemsetAsync(h0b,  0, Bc*Hc*sizeof(float));
    cudaMemsetAsync(h1b,  0, Bc*Hc*sizeof(float));
    cudaMemsetAsync(ctxb, 0, Bc*Hc*sizeof(float));

    // embeddings
    gather_rows<<<Lc*Bc, 128>>>(src_tokens, enc_embed, emb, 0);
    gather_rows<<<MBc,   128>>>(trgt_seq,   dec_embed, decemb, 1);

    // mlp_W2 conversion
    { long n = (long)Vc * 1024; conv_split<<<(unsigned)(n/256), 256>>>(mlp_W2, Bh, Bl, n, n); }

    // ===== encoder layer0 pre + persistent recurrence =====
    { long n = (long)Lc*Bc*Ec;  conv_split<<<(unsigned)(n/256), 256>>>(emb, Ah, Al, n, n); }
    { long n = (long)2*G3*Ec;   conv_split<<<(unsigned)(n/256), 256>>>(enc_Wih0, Wh, Wl, n, n); }
    gemm_bf16<<<dim3(Lc*Bc/128, 2*G3/128), 256, GEMM_SMEM>>>(
        Ec, Ah, Al, Wh, Wl, enc_bih0, gi, nullptr, nullptr, 2*G3, 0);
    enc_gru_persist<<<128, 256, ENC_SMEM>>>(gi, enc_Whh0, enc_bhh0, y0, bars + 0);

    // ===== encoder layer1 =====
    { long n = (long)Lc*Bc*2*Hc; conv_split<<<(unsigned)(n/256), 256>>>(y0, Ah, Al, n, n); }
    { long n = (long)2*G3*2*Hc;  conv_split<<<(unsigned)(n/256), 256>>>(enc_Wih1, Wh, Wl, n, n); }
    gemm_bf16<<<dim3(Lc*Bc/128, 2*G3/128), 256, GEMM_SMEM>>>(
        2*Hc, Ah, Al, Wh, Wl, enc_bih1, gi, nullptr, nullptr, 2*G3, 0);
    enc_gru_persist<<<128, 256, ENC_SMEM>>>(gi, enc_Whh1, enc_bhh1, y1, bars + 1);

    combine_enc<<<Lc*Bc, 128>>>(y1, eo);

    // ===== enc_q =====
    { long n = (long)Lc*Bc*Hc; conv_split<<<(unsigned)(n/256), 256>>>(eo, Ah, Al, n, n); }
    { long n = (long)Ac*Hc;    conv_split<<<(unsigned)(n/256), 256>>>(attn_We, Wh, Wl, n, n); }
    gemm_bf16<<<dim3(Lc*Bc/128, Ac/128), 256, GEMM_SMEM>>>(
        Hc, Ah, Al, Wh, Wl, attn_be, eq, nullptr, nullptr, Ac, 0);

    // ===== decoder pre =====
    { long nv = (long)MBc*Ec, nt = (long)MPAD*Ec;
      conv_split<<<(unsigned)(nt/256), 256>>>(decemb, Ah, Al, nv, nt); }
    { long n = (long)G3*Ec;
      conv_split2d<<<(unsigned)(n/256), 256>>>(dec_Wih0, Ec + Hc, G3, Ec, Wh, Wl); }
    gemm_bf16<<<dim3(MPAD/128, G3/128), 256, GEMM_SMEM>>>(
        Ec, Ah, Al, Wh, Wl, dec_bih0, dpre, nullptr, nullptr, G3, 0);

    // ===== persistent decoder (63 steps, 4 phases each) =====
    dec_persist<<<128, 128, DEC_SMEM>>>(
        dec_Wih0, dec_Whh0, dec_bhh0,
        dec_Wih1, dec_Whh1, dec_bih1, dec_bhh1,
        attn_Wd, attn_bd, dpre, eq, eo,
        h0b, h1b, ctxb, qb, feat, bars + 2);

    // ===== MLP1 (split-bf16 out) =====
    { long nv = (long)MBc*2*Hc, nt = (long)MPAD*2*Hc;
      conv_split<<<(unsigned)(nt/256), 256>>>(feat, Ah, Al, nv, nt); }
    { long n = (long)2*Hc*2*Hc; conv_split<<<(unsigned)(n/256), 256>>>(mlp_W1, Wh, Wl, n, n); }
    __nv_bfloat16* Ah2 = Ah + (size_t)MPAD * 1024;
    __nv_bfloat16* Al2 = Al + (size_t)MPAD * 1024;
    gemm_bf16<<<dim3(MPAD/128, 2*Hc/128), 256, GEMM_SMEM>>>(
        2*Hc, Ah, Al, Wh, Wl, mlp_b1, nullptr, Ah2, Al2, 2*Hc, F_RELU | F_SPLIT);

    // ===== MLP2 logits (M-fast grid: B read ~once from DRAM, A stays L2-hot) =====
    gemm_bf16<<<dim3(MPAD/128, Vc/128), 256, GEMM_SMEM>>>(
        2*Hc, Ah2, Al2, Bh, Bl, mlp_b2, (float*)d_out, nullptr, nullptr, Vc, F_REMAP);
}

// round 15
// speedup vs baseline: 1.0627x; 1.0627x over previous
#include <cuda_runtime.h>
#include <cuda_bf16.h>
#include <cstdint>
#include <math.h>

#define Lc 128
#define Bc 32
#define Tc 64
#define TDc 63
#define Ec 512
#define Hc 512
#define Ac 512
#define Vc 32000
#define G3 1536
#define MBc (TDc*Bc)   // 2016
#define MPAD 2048

// ---------------- scratch ----------------
__device__ float d_emb   [Lc*Bc*Ec];
__device__ float d_decemb[MBc*Ec];
__device__ float d_gi    [Lc*Bc*2*G3];
__device__ float d_y0    [Lc*Bc*2*Hc];
__device__ float d_y1    [Lc*Bc*2*Hc];
__device__ float d_eo    [Lc*Bc*Hc];
__device__ float d_eq    [Lc*Bc*Ac];
__device__ float d_dpre  [MPAD*G3];
__device__ float d_h0b   [2*Bc*Hc];
__device__ float d_h1b   [2*Bc*Hc];
__device__ float d_ctxb  [2*Bc*Hc];
__device__ float d_qb    [Bc*Ac];
__device__ float d_feat  [MBc*2*Hc];
__device__ unsigned d_bars[4];
// bf16 split operand buffers
__device__ __nv_bfloat16 d_Ah[4096*1024];
__device__ __nv_bfloat16 d_Al[4096*1024];
__device__ __nv_bfloat16 d_Wh[3072*1024];
__device__ __nv_bfloat16 d_Wl[3072*1024];
__device__ __nv_bfloat16 d_Bh[(size_t)Vc*1024];
__device__ __nv_bfloat16 d_Bl[(size_t)Vc*1024];

// ---------------- grid barrier (all blocks co-resident: grid <= 148) ---------------
__device__ __forceinline__ void gbar(unsigned* cnt, unsigned target) {
    __threadfence();
    __syncthreads();
    if (threadIdx.x == 0) {
        unsigned v;
        asm volatile("red.release.gpu.global.add.u32 [%0], 1;" :: "l"(cnt) : "memory");
        do {
            asm volatile("ld.acquire.gpu.global.u32 %0, [%1];" : "=r"(v) : "l"(cnt) : "memory");
        } while (v < target);
    }
    __syncthreads();
}

// ---------------- embedding gathers ----------------
__global__ void gather_rows(const int* __restrict__ tok, const float* __restrict__ tab,
                            float* __restrict__ out, int mode)
{
    int row = blockIdx.x;
    int idx;
    if (mode == 0) idx = tok[row];
    else { int t = row >> 5, b = row & 31; idx = tok[b*Tc + t]; }
    const float4* src = (const float4*)(tab + (size_t)idx * Ec);
    float4* dst = (float4*)(out + (size_t)row * Ec);
    dst[threadIdx.x] = src[threadIdx.x];
}

// ---------------- fp32 -> split bf16 ----------------
__global__ void conv_split(const float* __restrict__ in, __nv_bfloat16* __restrict__ hi,
                           __nv_bfloat16* __restrict__ lo, long n_valid, long n_total)
{
    long i = (long)blockIdx.x * blockDim.x + threadIdx.x;
    if (i >= n_total) return;
    float v = (i < n_valid) ? in[i] : 0.f;
    __nv_bfloat16 h = __float2bfloat16(v);
    hi[i] = h;
    lo[i] = __float2bfloat16(v - __bfloat162float(h));
}
__global__ void conv_split2d(const float* __restrict__ in, int ld, int rows, int cols,
                             __nv_bfloat16* __restrict__ hi, __nv_bfloat16* __restrict__ lo)
{
    long i = (long)blockIdx.x * blockDim.x + threadIdx.x;
    if (i >= (long)rows * cols) return;
    int r = (int)(i / cols), c = (int)(i % cols);
    float v = in[(size_t)r * ld + c];
    __nv_bfloat16 h = __float2bfloat16(v);
    hi[i] = h;
    lo[i] = __float2bfloat16(v - __bfloat162float(h));
}

// =============== generic split-bf16 tensor GEMM; grid: x = M-tiles (fast), y = N-tiles ========
// M-fast: a 148-block wave spans all M-tiles x few N-tiles -> B working set stays L2-hot,
// B streamed from DRAM ~once total (vs once per M-row with N-fast).
#define F_RELU  1
#define F_REMAP 2
#define F_SPLIT 4
#define SLDA 40
#define TILEB (128*SLDA*2)
#define STAGEB (4*TILEB)
#define GEMM_SMEM (2*STAGEB)

__device__ __forceinline__ uint32_t smem_u32(const void* p) {
    uint32_t a;
    asm("{ .reg .u64 t; cvta.to.shared.u64 t, %1; cvt.u32.u64 %0, t; }" : "=r"(a) : "l"(p));
    return a;
}
__device__ __forceinline__ void ldm4(uint32_t& r0, uint32_t& r1, uint32_t& r2, uint32_t& r3, uint32_t a) {
    asm volatile("ldmatrix.sync.aligned.m8n8.x4.shared.b16 {%0,%1,%2,%3}, [%4];"
                 : "=r"(r0), "=r"(r1), "=r"(r2), "=r"(r3) : "r"(a));
}
__device__ __forceinline__ void mma16816(float* c, const uint32_t* a, const uint32_t* b) {
    asm volatile("mma.sync.aligned.m16n8k16.row.col.f32.bf16.bf16.f32 "
                 "{%0,%1,%2,%3},{%4,%5,%6,%7},{%8,%9},{%0,%1,%2,%3};"
                 : "+f"(c[0]), "+f"(c[1]), "+f"(c[2]), "+f"(c[3])
                 : "r"(a[0]), "r"(a[1]), "r"(a[2]), "r"(a[3]), "r"(b[0]), "r"(b[1]));
}
#define CP16(dst, src) asm volatile("cp.async.cg.shared.global [%0], [%1], 16;" :: "r"(dst), "l"(src))
#define CP_COMMIT()    asm volatile("cp.async.commit_group;" ::: "memory")
#define CP_WAIT1()     asm volatile("cp.async.wait_group 1;" ::: "memory")

__global__ __launch_bounds__(256) void gemm_bf16(
    int K,
    const __nv_bfloat16* __restrict__ Ah, const __nv_bfloat16* __restrict__ Al,
    const __nv_bfloat16* __restrict__ Bh, const __nv_bfloat16* __restrict__ Bl,
    const float* __restrict__ bias,
    float* __restrict__ Cf, __nv_bfloat16* __restrict__ Chi, __nv_bfloat16* __restrict__ Clo,
    int ldc, int flags)
{
    extern __shared__ char smem[];
    const uint32_t smem_base = smem_u32(smem);
    const int tid = threadIdx.x, wid = tid >> 5, lane = tid & 31;
    const int mBase = blockIdx.x * 128;   // M fastest
    const int nBase = blockIdx.y * 128;
    const int warpM = (wid & 1) * 64;
    const int warpN = (wid >> 1) * 32;

    const __nv_bfloat16* g[4] = {
        Ah + (size_t)mBase * K, Al + (size_t)mBase * K,
        Bh + (size_t)nBase * K, Bl + (size_t)nBase * K };

    const int lRow0 = tid >> 2, lSc0 = (tid & 3);
    const int lRow1 = (tid + 256) >> 2, lSc1 = ((tid + 256) & 3);

    auto prefetch = [&](int st, int kc) {
        #pragma unroll
        for (int op = 0; op < 4; op++) {
            uint32_t sb = smem_base + st * STAGEB + op * TILEB;
            CP16(sb + (uint32_t)(lRow0 * SLDA + lSc0 * 8) * 2, g[op] + (size_t)lRow0 * K + kc + lSc0 * 8);
            CP16(sb + (uint32_t)(lRow1 * SLDA + lSc1 * 8) * 2, g[op] + (size_t)lRow1 * K + kc + lSc1 * 8);
        }
    };

    float acc[4][4][4];
    #pragma unroll
    for (int i = 0; i < 4; i++)
        #pragma unroll
        for (int j = 0; j < 4; j++)
            #pragma unroll
            for (int e = 0; e < 4; e++) acc[i][j][e] = 0.f;

    const int aRow = (lane & 15), aK = (lane >> 4) * 8;
    const int bRow = ((lane >> 4) << 3) + (lane & 7), bK = ((lane >> 3) & 1) * 8;

    const int nch = K >> 5;
    prefetch(0, 0);
    CP_COMMIT();

    for (int c = 0; c < nch; c++) {
        if (c + 1 < nch) prefetch((c + 1) & 1, (c + 1) << 5);
        CP_COMMIT();
        CP_WAIT1();
        __syncthreads();

        const uint32_t stb = smem_base + (c & 1) * STAGEB;
        const uint32_t bAh = stb, bAl = stb + TILEB, bBh = stb + 2*TILEB, bBl = stb + 3*TILEB;

        #pragma unroll
        for (int ks = 0; ks < 2; ks++) {
            const int kb = ks * 16;
            uint32_t fbh[4][2], fbl[4][2];
            #pragma unroll
            for (int nt = 0; nt < 2; nt++) {
                uint32_t off = ((uint32_t)(warpN + nt * 16 + bRow) * SLDA + kb + bK) * 2;
                ldm4(fbh[nt*2][0], fbh[nt*2][1], fbh[nt*2+1][0], fbh[nt*2+1][1], bBh + off);
                ldm4(fbl[nt*2][0], fbl[nt*2][1], fbl[nt*2+1][0], fbl[nt*2+1][1], bBl + off);
            }
            #pragma unroll
            for (int mi = 0; mi < 4; mi++) {
                uint32_t fah[4], fal[4];
                uint32_t off = ((uint32_t)(warpM + mi * 16 + aRow) * SLDA + kb + aK) * 2;
                ldm4(fah[0], fah[1], fah[2], fah[3], bAh + off);
                ldm4(fal[0], fal[1], fal[2], fal[3], bAl + off);
                #pragma unroll
                for (int ni = 0; ni < 4; ni++) {
                    mma16816(acc[mi][ni], fah, fbh[ni]);
                    mma16816(acc[mi][ni], fah, fbl[ni]);
                    mma16816(acc[mi][ni], fal, fbh[ni]);
                }
            }
        }
        __syncthreads();
    }

    const int mLane = lane >> 2;
    const int nLane = (lane & 3) * 2;
    #pragma unroll
    for (int mi = 0; mi < 4; mi++) {
        #pragma unroll
        for (int half = 0; half < 2; half++) {
            int m = mBase + warpM + mi * 16 + mLane + half * 8;
            int orow = m;
            if (flags & F_REMAP) {
                if (m >= MBc) continue;
                orow = (m & 31) * TDc + (m >> 5);
            }
            #pragma unroll
            for (int ni = 0; ni < 4; ni++) {
                int n = nBase + warpN + ni * 8 + nLane;
                float vx = acc[mi][ni][half * 2 + 0] + bias[n];
                float vy = acc[mi][ni][half * 2 + 1] + bias[n + 1];
                if (flags & F_RELU) { vx = fmaxf(vx, 0.f); vy = fmaxf(vy, 0.f); }
                if (flags & F_SPLIT) {
                    size_t o = (size_t)orow * ldc + n;
                    __nv_bfloat16 hx = __float2bfloat16(vx), hy = __float2bfloat16(vy);
                    Chi[o] = hx; Chi[o+1] = hy;
                    Clo[o]   = __float2bfloat16(vx - __bfloat162float(hx));
                    Clo[o+1] = __float2bfloat16(vy - __bfloat162float(hy));
                } else {
                    *(float2*)(Cf + (size_t)orow * ldc + n) = make_float2(vx, vy);
                }
            }
        }
    }
}

// ---------------- shared helpers for recurrent kernels (R9 float4 versions) ----------------
__device__ __forceinline__ void gate3_chunk(
    const float (*hs)[132], int row, const float* pr, const float* pz, const float* pn,
    float& a0, float& a1, float& a2)
{
    #pragma unroll 8
    for (int k = 0; k < 128; k += 4) {
        float4 hv = *(const float4*)&hs[row][k];
        float4 w4;
        w4 = *(const float4*)&pr[k]; a0 += hv.x*w4.x + hv.y*w4.y + hv.z*w4.z + hv.w*w4.w;
        w4 = *(const float4*)&pz[k]; a1 += hv.x*w4.x + hv.y*w4.y + hv.z*w4.z + hv.w*w4.w;
        w4 = *(const float4*)&pn[k]; a2 += hv.x*w4.x + hv.y*w4.y + hv.z*w4.z + hv.w*w4.w;
    }
}
__device__ __forceinline__ void stage_tile(float (*hs)[132], const float* src, int kc, int nthr, int tid) {
    for (int i = tid; i < 1024; i += nthr) {
        int r = i >> 5, kk = (i & 31) << 2;
        *(float4*)&hs[r][kk] = *(const float4*)&src[(size_t)r*Hc + kc + kk];
    }
}

// =============== persistent encoder GRU layer: 128 blocks, 128 steps internal ===============
#define ENC_SMEM (49152 + 32*132*4)
__global__ __launch_bounds__(256) void enc_gru_persist(
    const float* __restrict__ gi, const float* __restrict__ WhhBase,
    const float* __restrict__ bhhBase, float* __restrict__ y, unsigned* bar)
{
    extern __shared__ char sm[];
    float* wsm = (float*)sm;                            // [3][8][512]
    float (*hs)[132] = (float(*)[132])(sm + 49152);
    const int tid = threadIdx.x, wid = tid >> 5, row = tid & 31;
    const int dir = blockIdx.x >> 6;
    const int jb  = blockIdx.x & 63;
    const int j   = jb * 8 + wid;
    const int dcol = dir * Hc;
    const float* Whh = WhhBase + (size_t)dir * G3 * Hc;
    const float* bhh = bhhBase + dir * G3;

    for (int i = tid; i < 3*8*512; i += 256) {
        int g = i >> 12, rem = i & 4095, w = rem >> 9, k = rem & 511;
        wsm[i] = Whh[(size_t)(g*Hc + jb*8 + w)*Hc + k];
    }
    const float b0 = bhh[j], b1 = bhh[Hc + j], b2 = bhh[2*Hc + j];
    __syncthreads();

    for (int s = 0; s < Lc; s++) {
        const int te = dir ? (Lc - 1 - s) : s;
        const int tprev = dir ? (te + 1) : (te - 1);
        const bool first = (s == 0);
        float ar = 0.f, az = 0.f, an = 0.f;
        for (int kc = 0; kc < Hc; kc += 128) {
            for (int i = tid; i < 1024; i += 256) {
                int r = i >> 5, kk = (i & 31) << 2;
                float4 v = make_float4(0,0,0,0);
                if (!first) v = *(const float4*)&y[((size_t)tprev*Bc + r)*(2*Hc) + dcol + kc + kk];
                *(float4*)&hs[r][kk] = v;
            }
            __syncthreads();
            gate3_chunk(hs, row, wsm + wid*512 + kc, wsm + 4096 + wid*512 + kc,
                        wsm + 8192 + wid*512 + kc, ar, az, an);
            __syncthreads();
        }
        const float* gp = gi + ((size_t)te*Bc + row) * (2*G3) + dir * G3;
        float rg = 1.f / (1.f + __expf(-(gp[j]      + ar + b0)));
        float zg = 1.f / (1.f + __expf(-(gp[Hc + j] + az + b1)));
        float ng = tanhf(gp[2*Hc + j] + rg * (an + b2));
        float hp = first ? 0.f : y[((size_t)tprev*Bc + row)*(2*Hc) + dcol + j];
        y[((size_t)te*Bc + row)*(2*Hc) + dcol + j] = (1.f - zg)*ng + zg*hp;
        if (s < Lc - 1) gbar(bar, 128u * (unsigned)(s + 1));
    }
}

// ---------------- enc_out = y1[:, :H] + y1[:, H:] ----------------
__global__ void combine_enc(const float* __restrict__ y1, float* __restrict__ eo)
{
    int i = blockIdx.x;
    int h = threadIdx.x * 4;
    float4 a = *(const float4*)&y1[(size_t)i*2*Hc + h];
    float4 b = *(const float4*)&y1[(size_t)i*2*Hc + Hc + h];
    *(float4*)&eo[(size_t)i*Hc + h] = make_float4(a.x+b.x, a.y+b.y, a.z+b.z, a.w+b.w);
}

// =============== persistent decoder: 128 blocks x 128 thr, 63 steps x 4 phases ===============
#define DEC_SMEM (4*24576 + 8192 + 32*132*4 + (512+128+4)*4)
__global__ __launch_bounds__(128) void dec_persist(
    const float* __restrict__ dWih0, const float* __restrict__ dWhh0,
    const float* __restrict__ bhh0,
    const float* __restrict__ dWih1, const float* __restrict__ dWhh1,
    const float* __restrict__ bih1, const float* __restrict__ bhh1,
    const float* __restrict__ Wd, const float* __restrict__ bd,
    const float* __restrict__ dpre,
    const float* __restrict__ encq, const float* __restrict__ encout,
    float* __restrict__ h0b, float* __restrict__ h1b, float* __restrict__ ctxb,
    float* __restrict__ qb, float* __restrict__ feat, unsigned* bar)
{
    extern __shared__ char sm[];
    float* wx0 = (float*)sm;                 // each [3][4][512] = 6144 floats
    float* wh0 = wx0 + 6144;
    float* wx1 = wh0 + 6144;
    float* wh1 = wx1 + 6144;
    float* wd  = wh1 + 6144;                 // [4][512]
    float (*hs)[132] = (float(*)[132])(wd + 2048);
    float* qs   = (float*)hs + 32*132;       // 512
    float* es   = qs + 512;                  // 128
    float* ssum = es + 128;                  // 4

    const int tid = threadIdx.x, w = tid >> 5, lane = tid & 31, row = lane;
    const int blk = blockIdx.x;
    const int j = blk * 4 + w;

    for (int i = tid; i < 6144; i += 128) {
        int g = i / 2048, rem = i - g*2048, ww = rem >> 9, k = rem & 511;
        int r0 = g*Hc + blk*4 + ww;
        wx0[i] = dWih0[(size_t)r0*(Ec + Hc) + Ec + k];
        wh0[i] = dWhh0[(size_t)r0*Hc + k];
        wx1[i] = dWih1[(size_t)r0*Hc + k];
        wh1[i] = dWhh1[(size_t)r0*Hc + k];
    }
    for (int i = tid; i < 2048; i += 128)
        wd[i] = Wd[(size_t)(blk*4 + (i >> 9))*Hc + (i & 511)];
    const float bh0r = bhh0[j], bh0z = bhh0[Hc+j], bh0n = bhh0[2*Hc+j];
    const float bi1r = bih1[j], bi1z = bih1[Hc+j], bi1n = bih1[2*Hc+j];
    const float bh1r = bhh1[j], bh1z = bhh1[Hc+j], bh1n = bhh1[2*Hc+j];
    const float bdj = bd[j];
    __syncthreads();

    unsigned bi = 0;
    for (int t = 0; t < TDc; t++) {
        const int r = t & 1, wix = 1 - r;
        const float* ctxp = ctxb + (size_t)r*Bc*Hc;
        const float* h0p  = h0b  + (size_t)r*Bc*Hc;
        float*       h0n  = h0b  + (size_t)wix*Bc*Hc;
        const float* h1p  = h1b  + (size_t)r*Bc*Hc;
        float*       h1n  = h1b  + (size_t)wix*Bc*Hc;

        // ---- phase 1: cell0 (x=ctx, h=h0) ----
        {
            float air=0.f, aiz=0.f, ain=0.f, ahr=0.f, ahz=0.f, ahn=0.f;
            for (int kc = 0; kc < Hc; kc += 128) {
                stage_tile(hs, ctxp, kc, 128, tid);
                __syncthreads();
                gate3_chunk(hs, row, wx0 + w*512 + kc, wx0 + 2048 + w*512 + kc,
                            wx0 + 4096 + w*512 + kc, air, aiz, ain);
                __syncthreads();
            }
            for (int kc = 0; kc < Hc; kc += 128) {
                stage_tile(hs, h0p, kc, 128, tid);
                __syncthreads();
                gate3_chunk(hs, row, wh0 + w*512 + kc, wh0 + 2048 + w*512 + kc,
                            wh0 + 4096 + w*512 + kc, ahr, ahz, ahn);
                __syncthreads();
            }
            const float* pre = dpre + ((size_t)t*Bc + row)*G3;
            float rg = 1.f / (1.f + __expf(-(air + pre[j]      + ahr + bh0r)));
            float zg = 1.f / (1.f + __expf(-(aiz + pre[Hc+j]   + ahz + bh0z)));
            float ng = tanhf(ain + pre[2*Hc+j] + rg * (ahn + bh0n));
            h0n[(size_t)row*Hc + j] = (1.f - zg)*ng + zg*h0p[(size_t)row*Hc + j];
        }
        gbar(bar, 128u * (++bi));

        // ---- phase 2: cell1 (x=h0n, h=h1) ----
        {
            float air=0.f, aiz=0.f, ain=0.f, ahr=0.f, ahz=0.f, ahn=0.f;
            for (int kc = 0; kc < Hc; kc += 128) {
                stage_tile(hs, h0n, kc, 128, tid);
                __syncthreads();
                gate3_chunk(hs, row, wx1 + w*512 + kc, wx1 + 2048 + w*512 + kc,
                            wx1 + 4096 + w*512 + kc, air, aiz, ain);
                __syncthreads();
            }
            for (int kc = 0; kc < Hc; kc += 128) {
                stage_tile(hs, h1p, kc, 128, tid);
                __syncthreads();
                gate3_chunk(hs, row, wh1 + w*512 + kc, wh1 + 2048 + w*512 + kc,
                            wh1 + 4096 + w*512 + kc, ahr, ahz, ahn);
                __syncthreads();
            }
            float rg = 1.f / (1.f + __expf(-(air + bi1r + ahr + bh1r)));
            float zg = 1.f / (1.f + __expf(-(aiz + bi1z + ahz + bh1z)));
            float ng = tanhf(ain + bi1n + rg * (ahn + bh1n));
            h1n[(size_t)row*Hc + j] = (1.f - zg)*ng + zg*h1p[(size_t)row*Hc + j];
        }
        gbar(bar, 128u * (++bi));

        // ---- phase 3: q = h1n @ Wd^T + bd ----
        {
            float acc = 0.f;
            for (int kc = 0; kc < Hc; kc += 128) {
                stage_tile(hs, h1n, kc, 128, tid);
                __syncthreads();
                const float* wj = wd + w*512 + kc;
                #pragma unroll 8
                for (int k = 0; k < 128; k += 4) {
                    float4 hv = *(const float4*)&hs[row][k];
                    float4 w4 = *(const float4*)&wj[k];
                    acc += hv.x*w4.x + hv.y*w4.y + hv.z*w4.z + hv.w*w4.w;
                }
                __syncthreads();
            }
            qb[(size_t)row*Hc + j] = acc + bdj;
        }
        gbar(bar, 128u * (++bi));

        // ---- phase 4: attention + feat (blocks 0..31, b = blk) ----
        if (blk < 32) {
            const int b = blk;
            qs[tid]       = qb[(size_t)b*Hc + tid];
            qs[tid + 128] = qb[(size_t)b*Hc + tid + 128];
            qs[tid + 256] = qb[(size_t)b*Hc + tid + 256];
            qs[tid + 384] = qb[(size_t)b*Hc + tid + 384];
            __syncthreads();
            for (int l = w; l < Lc; l += 4) {
                const float* eqr = encq + ((size_t)l*Bc + b) * Ac;
                float s = 0.f;
                #pragma unroll
                for (int qk = 0; qk < 4; qk++) {
                    int k = qk*128 + lane*4;
                    float4 a = *(const float4*)&eqr[k];
                    float4 c = *(const float4*)&qs[k];
                    s += a.x*c.x + a.y*c.y + a.z*c.z + a.w*c.w;
                }
                #pragma unroll
                for (int off = 16; off; off >>= 1) s += __shfl_xor_sync(0xffffffffu, s, off);
                if (lane == 0) es[l] = __expf(tanhf(s));
            }
            __syncthreads();
            {
                float v = es[tid];
                #pragma unroll
                for (int off = 16; off; off >>= 1) v += __shfl_xor_sync(0xffffffffu, v, off);
                if (lane == 0) ssum[w] = v;
            }
            __syncthreads();
            float inv = 1.f / (ssum[0] + ssum[1] + ssum[2] + ssum[3]);
            float a0=0.f, a1=0.f, a2=0.f, a3=0.f;
            for (int l = 0; l < Lc; l++) {
                float wl = es[l];
                const float* eor = encout + ((size_t)l*Bc + b) * Hc;
                a0 += wl*eor[tid]; a1 += wl*eor[tid+128]; a2 += wl*eor[tid+256]; a3 += wl*eor[tid+384];
            }
            a0 *= inv; a1 *= inv; a2 *= inv; a3 *= inv;
            float* cx = ctxb + (size_t)wix*Bc*Hc + (size_t)b*Hc;
            cx[tid]=a0; cx[tid+128]=a1; cx[tid+256]=a2; cx[tid+384]=a3;
            float* fp = feat + ((size_t)t*Bc + b) * 2*Hc;
            const float* h1r = h1n + (size_t)b*Hc;
            fp[tid]=h1r[tid]; fp[tid+128]=h1r[tid+128]; fp[tid+256]=h1r[tid+256]; fp[tid+384]=h1r[tid+384];
            fp[Hc+tid]=a0; fp[Hc+tid+128]=a1; fp[Hc+tid+256]=a2; fp[Hc+tid+384]=a3;
            __syncthreads();
        }
        ++bi;
        if (t < TDc - 1) gbar(bar, 128u * bi);
    }
}

// ================================================================================
extern "C" void kernel_launch(void* const* d_in, const int* in_sizes, int n_in,
                              void* d_out, int out_size)
{
    const int*   src_tokens = (const int*)  d_in[0];
    const int*   trgt_seq   = (const int*)  d_in[1];
    const float* enc_embed  = (const float*)d_in[3];
    const float* enc_Wih0   = (const float*)d_in[4];
    const float* enc_Whh0   = (const float*)d_in[5];
    const float* enc_bih0   = (const float*)d_in[6];
    const float* enc_bhh0   = (const float*)d_in[7];
    const float* enc_Wih1   = (const float*)d_in[8];
    const float* enc_Whh1   = (const float*)d_in[9];
    const float* enc_bih1   = (const float*)d_in[10];
    const float* enc_bhh1   = (const float*)d_in[11];
    const float* dec_embed  = (const float*)d_in[12];
    const float* dec_Wih0   = (const float*)d_in[13];
    const float* dec_Whh0   = (const float*)d_in[14];
    const float* dec_bih0   = (const float*)d_in[15];
    const float* dec_bhh0   = (const float*)d_in[16];
    const float* dec_Wih1   = (const float*)d_in[17];
    const float* dec_Whh1   = (const float*)d_in[18];
    const float* dec_bih1   = (const float*)d_in[19];
    const float* dec_bhh1   = (const float*)d_in[20];
    const float* attn_We    = (const float*)d_in[21];
    const float* attn_be    = (const float*)d_in[22];
    const float* attn_Wd    = (const float*)d_in[23];
    const float* attn_bd    = (const float*)d_in[24];
    const float* mlp_W1     = (const float*)d_in[25];
    const float* mlp_b1     = (const float*)d_in[26];
    const float* mlp_W2     = (const float*)d_in[27];
    const float* mlp_b2     = (const float*)d_in[28];

    float *emb, *decemb, *gi, *y0, *y1, *eo, *eq, *dpre, *h0b, *h1b, *ctxb, *qb, *feat;
    unsigned* bars;
    __nv_bfloat16 *Ah, *Al, *Wh, *Wl, *Bh, *Bl;
    cudaGetSymbolAddress((void**)&emb,    d_emb);
    cudaGetSymbolAddress((void**)&decemb, d_decemb);
    cudaGetSymbolAddress((void**)&gi,     d_gi);
    cudaGetSymbolAddress((void**)&y0,     d_y0);
    cudaGetSymbolAddress((void**)&y1,     d_y1);
    cudaGetSymbolAddress((void**)&eo,     d_eo);
    cudaGetSymbolAddress((void**)&eq,     d_eq);
    cudaGetSymbolAddress((void**)&dpre,   d_dpre);
    cudaGetSymbolAddress((void**)&h0b,    d_h0b);
    cudaGetSymbolAddress((void**)&h1b,    d_h1b);
    cudaGetSymbolAddress((void**)&ctxb,   d_ctxb);
    cudaGetSymbolAddress((void**)&qb,     d_qb);
    cudaGetSymbolAddress((void**)&feat,   d_feat);
    cudaGetSymbolAddress((void**)&bars,   d_bars);
    cudaGetSymbolAddress((void**)&Ah,     d_Ah);
    cudaGetSymbolAddress((void**)&Al,     d_Al);
    cudaGetSymbolAddress((void**)&Wh,     d_Wh);
    cudaGetSymbolAddress((void**)&Wl,     d_Wl);
    cudaGetSymbolAddress((void**)&Bh,     d_Bh);
    cudaGetSymbolAddress((void**)&Bl,     d_Bl);

    cudaFuncSetAttribute(gemm_bf16,       cudaFuncAttributeMaxDynamicSharedMemorySize, GEMM_SMEM);
    cudaFuncSetAttribute(enc_gru_persist, cudaFuncAttributeMaxDynamicSharedMemorySize, ENC_SMEM);
    cudaFuncSetAttribute(dec_persist,     cudaFuncAttributeMaxDynamicSharedMemorySize, DEC_SMEM);

    cudaMemsetAsync(bars, 0, 4*sizeof(unsigned));
    cudaMemsetAsync(h0b,  0, Bc*Hc*sizeof(float));
    cudaMemsetAsync(h1b,  0, Bc*Hc*sizeof(float));
    cudaMemsetAsync(ctxb, 0, Bc*Hc*sizeof(float));

    // embeddings
    gather_rows<<<Lc*Bc, 128>>>(src_tokens, enc_embed, emb, 0);
    gather_rows<<<MBc,   128>>>(trgt_seq,   dec_embed, decemb, 1);

    // mlp_W2 conversion
    { long n = (long)Vc * 1024; conv_split<<<(unsigned)(n/256), 256>>>(mlp_W2, Bh, Bl, n, n); }

    // ===== encoder layer0 pre + persistent recurrence =====
    { long n = (long)Lc*Bc*Ec;  conv_split<<<(unsigned)(n/256), 256>>>(emb, Ah, Al, n, n); }
    { long n = (long)2*G3*Ec;   conv_split<<<(unsigned)(n/256), 256>>>(enc_Wih0, Wh, Wl, n, n); }
    gemm_bf16<<<dim3(Lc*Bc/128, 2*G3/128), 256, GEMM_SMEM>>>(
        Ec, Ah, Al, Wh, Wl, enc_bih0, gi, nullptr, nullptr, 2*G3, 0);
    enc_gru_persist<<<128, 256, ENC_SMEM>>>(gi, enc_Whh0, enc_bhh0, y0, bars + 0);

    // ===== encoder layer1 =====
    { long n = (long)Lc*Bc*2*Hc; conv_split<<<(unsigned)(n/256), 256>>>(y0, Ah, Al, n, n); }
    { long n = (long)2*G3*2*Hc;  conv_split<<<(unsigned)(n/256), 256>>>(enc_Wih1, Wh, Wl, n, n); }
    gemm_bf16<<<dim3(Lc*Bc/128, 2*G3/128), 256, GEMM_SMEM>>>(
        2*Hc, Ah, Al, Wh, Wl, enc_bih1, gi, nullptr, nullptr, 2*G3, 0);
    enc_gru_persist<<<128, 256, ENC_SMEM>>>(gi, enc_Whh1, enc_bhh1, y1, bars + 1);

    combine_enc<<<Lc*Bc, 128>>>(y1, eo);

    // ===== enc_q =====
    { long n = (long)Lc*Bc*Hc; conv_split<<<(unsigned)(n/256), 256>>>(eo, Ah, Al, n, n); }
    { long n = (long)Ac*Hc;    conv_split<<<(unsigned)(n/256), 256>>>(attn_We, Wh, Wl, n, n); }
    gemm_bf16<<<dim3(Lc*Bc/128, Ac/128), 256, GEMM_SMEM>>>(
        Hc, Ah, Al, Wh, Wl, attn_be, eq, nullptr, nullptr, Ac, 0);

    // ===== decoder pre =====
    { long nv = (long)MBc*Ec, nt = (long)MPAD*Ec;
      conv_split<<<(unsigned)(nt/256), 256>>>(decemb, Ah, Al, nv, nt); }
    { long n = (long)G3*Ec;
      conv_split2d<<<(unsigned)(n/256), 256>>>(dec_Wih0, Ec + Hc, G3, Ec, Wh, Wl); }
    gemm_bf16<<<dim3(MPAD/128, G3/128), 256, GEMM_SMEM>>>(
        Ec, Ah, Al, Wh, Wl, dec_bih0, dpre, nullptr, nullptr, G3, 0);

    // ===== persistent decoder (63 steps, 4 phases each) =====
    dec_persist<<<128, 128, DEC_SMEM>>>(
        dec_Wih0, dec_Whh0, dec_bhh0,
        dec_Wih1, dec_Whh1, dec_bih1, dec_bhh1,
        attn_Wd, attn_bd, dpre, eq, eo,
        h0b, h1b, ctxb, qb, feat, bars + 2);

    // ===== MLP1 (split-bf16 out) =====
    { long nv = (long)MBc*2*Hc, nt = (long)MPAD*2*Hc;
      conv_split<<<(unsigned)(nt/256), 256>>>(feat, Ah, Al, nv, nt); }
    { long n = (long)2*Hc*2*Hc; conv_split<<<(unsigned)(n/256), 256>>>(mlp_W1, Wh, Wl, n, n); }
    __nv_bfloat16* Ah2 = Ah + (size_t)MPAD * 1024;
    __nv_bfloat16* Al2 = Al + (size_t)MPAD * 1024;
    gemm_bf16<<<dim3(MPAD/128, 2*Hc/128), 256, GEMM_SMEM>>>(
        2*Hc, Ah, Al, Wh, Wl, mlp_b1, nullptr, Ah2, Al2, 2*Hc, F_RELU | F_SPLIT);

    // ===== MLP2 logits (M-fast grid: B streamed from DRAM once, not once per M-row) =====
    gemm_bf16<<<dim3(MPAD/128, Vc/128), 256, GEMM_SMEM>>>(
        2*Hc, Ah2, Al2, Bh, Bl, mlp_b2, (float*)d_out, nullptr, nullptr, Vc, F_REMAP);
}

// round 16
// speedup vs baseline: 1.0657x; 1.0029x over previous
#include <cuda_runtime.h>
#include <cuda_bf16.h>
#include <cstdint>
#include <math.h>

#define Lc 128
#define Bc 32
#define Tc 64
#define TDc 63
#define Ec 512
#define Hc 512
#define Ac 512
#define Vc 32000
#define G3 1536
#define MBc (TDc*Bc)   // 2016
#define MPAD 2048

// ---------------- scratch ----------------
__device__ float d_emb   [Lc*Bc*Ec];
__device__ float d_decemb[MBc*Ec];
__device__ float d_gi    [Lc*Bc*2*G3];
__device__ float d_y0    [Lc*Bc*2*Hc];
__device__ float d_y1    [Lc*Bc*2*Hc];
__device__ float d_eo    [Lc*Bc*Hc];
__device__ float d_eq    [Lc*Bc*Ac];
__device__ float d_dpre  [MPAD*G3];
__device__ float d_h0b   [2*Bc*Hc];
__device__ float d_h1b   [2*Bc*Hc];
__device__ float d_ctxb  [2*Bc*Hc];
__device__ float d_qb    [Bc*Ac];
__device__ float d_feat  [MBc*2*Hc];
__device__ unsigned d_bars[4];
// bf16 split operand buffers
__device__ __nv_bfloat16 d_Ah[4096*1024];
__device__ __nv_bfloat16 d_Al[4096*1024];
__device__ __nv_bfloat16 d_Wh[3072*1024];
__device__ __nv_bfloat16 d_Wl[3072*1024];
__device__ __nv_bfloat16 d_Bh[(size_t)Vc*1024];
__device__ __nv_bfloat16 d_Bl[(size_t)Vc*1024];

// ---------------- grid barrier (all blocks co-resident: grid <= 148) ---------------
__device__ __forceinline__ void gbar(unsigned* cnt, unsigned target) {
    __threadfence();
    __syncthreads();
    if (threadIdx.x == 0) {
        unsigned v;
        asm volatile("red.release.gpu.global.add.u32 [%0], 1;" :: "l"(cnt) : "memory");
        do {
            asm volatile("ld.acquire.gpu.global.u32 %0, [%1];" : "=r"(v) : "l"(cnt) : "memory");
        } while (v < target);
    }
    __syncthreads();
}

// ---------------- embedding gathers ----------------
__global__ void gather_rows(const int* __restrict__ tok, const float* __restrict__ tab,
                            float* __restrict__ out, int mode)
{
    int row = blockIdx.x;
    int idx;
    if (mode == 0) idx = tok[row];
    else { int t = row >> 5, b = row & 31; idx = tok[b*Tc + t]; }
    const float4* src = (const float4*)(tab + (size_t)idx * Ec);
    float4* dst = (float4*)(out + (size_t)row * Ec);
    dst[threadIdx.x] = src[threadIdx.x];
}

// ---------------- fp32 -> split bf16, 4-wide vectorized ----------------
__device__ __forceinline__ void split1(float v, __nv_bfloat16& h, __nv_bfloat16& l) {
    h = __float2bfloat16(v);
    l = __float2bfloat16(v - __bfloat162float(h));
}
__global__ void conv_split4(const float* __restrict__ in, __nv_bfloat16* __restrict__ hi,
                            __nv_bfloat16* __restrict__ lo, long n_valid, long n_total)
{
    long i = ((long)blockIdx.x * blockDim.x + threadIdx.x) * 4;
    if (i >= n_total) return;
    float4 v = (i + 3 < n_valid) ? *(const float4*)(in + i) : make_float4(
        (i   < n_valid) ? in[i]   : 0.f, (i+1 < n_valid) ? in[i+1] : 0.f,
        (i+2 < n_valid) ? in[i+2] : 0.f, (i+3 < n_valid) ? in[i+3] : 0.f);
    __nv_bfloat16 h[4], l[4];
    split1(v.x, h[0], l[0]); split1(v.y, h[1], l[1]);
    split1(v.z, h[2], l[2]); split1(v.w, h[3], l[3]);
    *(ulonglong1*)(hi + i) = *(ulonglong1*)h;
    *(ulonglong1*)(lo + i) = *(ulonglong1*)l;
}
__global__ void conv_split2d4(const float* __restrict__ in, int ld, int rows, int cols,
                              __nv_bfloat16* __restrict__ hi, __nv_bfloat16* __restrict__ lo)
{
    long i = ((long)blockIdx.x * blockDim.x + threadIdx.x) * 4;
    if (i >= (long)rows * cols) return;
    int r = (int)(i / cols), c = (int)(i % cols);     // cols % 4 == 0 at all call sites
    float4 v = *(const float4*)(in + (size_t)r * ld + c);
    __nv_bfloat16 h[4], l[4];
    split1(v.x, h[0], l[0]); split1(v.y, h[1], l[1]);
    split1(v.z, h[2], l[2]); split1(v.w, h[3], l[3]);
    *(ulonglong1*)(hi + i) = *(ulonglong1*)h;
    *(ulonglong1*)(lo + i) = *(ulonglong1*)l;
}

// =============== generic split-bf16 tensor GEMM (R9: x = N-tiles, y = M-tiles) ===============
#define F_RELU  1
#define F_REMAP 2
#define F_SPLIT 4
#define SLDA 40
#define TILEB (128*SLDA*2)
#define STAGEB (4*TILEB)
#define GEMM_SMEM (2*STAGEB)

__device__ __forceinline__ uint32_t smem_u32(const void* p) {
    uint32_t a;
    asm("{ .reg .u64 t; cvta.to.shared.u64 t, %1; cvt.u32.u64 %0, t; }" : "=r"(a) : "l"(p));
    return a;
}
__device__ __forceinline__ void ldm4(uint32_t& r0, uint32_t& r1, uint32_t& r2, uint32_t& r3, uint32_t a) {
    asm volatile("ldmatrix.sync.aligned.m8n8.x4.shared.b16 {%0,%1,%2,%3}, [%4];"
                 : "=r"(r0), "=r"(r1), "=r"(r2), "=r"(r3) : "r"(a));
}
__device__ __forceinline__ void mma16816(float* c, const uint32_t* a, const uint32_t* b) {
    asm volatile("mma.sync.aligned.m16n8k16.row.col.f32.bf16.bf16.f32 "
                 "{%0,%1,%2,%3},{%4,%5,%6,%7},{%8,%9},{%0,%1,%2,%3};"
                 : "+f"(c[0]), "+f"(c[1]), "+f"(c[2]), "+f"(c[3])
                 : "r"(a[0]), "r"(a[1]), "r"(a[2]), "r"(a[3]), "r"(b[0]), "r"(b[1]));
}
#define CP16(dst, src) asm volatile("cp.async.cg.shared.global [%0], [%1], 16;" :: "r"(dst), "l"(src))
#define CP_COMMIT()    asm volatile("cp.async.commit_group;" ::: "memory")
#define CP_WAIT1()     asm volatile("cp.async.wait_group 1;" ::: "memory")

__global__ __launch_bounds__(256) void gemm_bf16(
    int K,
    const __nv_bfloat16* __restrict__ Ah, const __nv_bfloat16* __restrict__ Al,
    const __nv_bfloat16* __restrict__ Bh, const __nv_bfloat16* __restrict__ Bl,
    const float* __restrict__ bias,
    float* __restrict__ Cf, __nv_bfloat16* __restrict__ Chi, __nv_bfloat16* __restrict__ Clo,
    int ldc, int flags)
{
    extern __shared__ char smem[];
    const uint32_t smem_base = smem_u32(smem);
    const int tid = threadIdx.x, wid = tid >> 5, lane = tid & 31;
    const int nBase = blockIdx.x * 128;
    const int mBase = blockIdx.y * 128;
    const int warpM = (wid & 1) * 64;
    const int warpN = (wid >> 1) * 32;

    const __nv_bfloat16* g[4] = {
        Ah + (size_t)mBase * K, Al + (size_t)mBase * K,
        Bh + (size_t)nBase * K, Bl + (size_t)nBase * K };

    const int lRow0 = tid >> 2, lSc0 = (tid & 3);
    const int lRow1 = (tid + 256) >> 2, lSc1 = ((tid + 256) & 3);

    auto prefetch = [&](int st, int kc) {
        #pragma unroll
        for (int op = 0; op < 4; op++) {
            uint32_t sb = smem_base + st * STAGEB + op * TILEB;
            CP16(sb + (uint32_t)(lRow0 * SLDA + lSc0 * 8) * 2, g[op] + (size_t)lRow0 * K + kc + lSc0 * 8);
            CP16(sb + (uint32_t)(lRow1 * SLDA + lSc1 * 8) * 2, g[op] + (size_t)lRow1 * K + kc + lSc1 * 8);
        }
    };

    float acc[4][4][4];
    #pragma unroll
    for (int i = 0; i < 4; i++)
        #pragma unroll
        for (int j = 0; j < 4; j++)
            #pragma unroll
            for (int e = 0; e < 4; e++) acc[i][j][e] = 0.f;

    const int aRow = (lane & 15), aK = (lane >> 4) * 8;
    const int bRow = ((lane >> 4) << 3) + (lane & 7), bK = ((lane >> 3) & 1) * 8;

    const int nch = K >> 5;
    prefetch(0, 0);
    CP_COMMIT();

    for (int c = 0; c < nch; c++) {
        if (c + 1 < nch) prefetch((c + 1) & 1, (c + 1) << 5);
        CP_COMMIT();
        CP_WAIT1();
        __syncthreads();

        const uint32_t stb = smem_base + (c & 1) * STAGEB;
        const uint32_t bAh = stb, bAl = stb + TILEB, bBh = stb + 2*TILEB, bBl = stb + 3*TILEB;

        #pragma unroll
        for (int ks = 0; ks < 2; ks++) {
            const int kb = ks * 16;
            uint32_t fbh[4][2], fbl[4][2];
            #pragma unroll
            for (int nt = 0; nt < 2; nt++) {
                uint32_t off = ((uint32_t)(warpN + nt * 16 + bRow) * SLDA + kb + bK) * 2;
                ldm4(fbh[nt*2][0], fbh[nt*2][1], fbh[nt*2+1][0], fbh[nt*2+1][1], bBh + off);
                ldm4(fbl[nt*2][0], fbl[nt*2][1], fbl[nt*2+1][0], fbl[nt*2+1][1], bBl + off);
            }
            #pragma unroll
            for (int mi = 0; mi < 4; mi++) {
                uint32_t fah[4], fal[4];
                uint32_t off = ((uint32_t)(warpM + mi * 16 + aRow) * SLDA + kb + aK) * 2;
                ldm4(fah[0], fah[1], fah[2], fah[3], bAh + off);
                ldm4(fal[0], fal[1], fal[2], fal[3], bAl + off);
                #pragma unroll
                for (int ni = 0; ni < 4; ni++) {
                    mma16816(acc[mi][ni], fah, fbh[ni]);
                    mma16816(acc[mi][ni], fah, fbl[ni]);
                    mma16816(acc[mi][ni], fal, fbh[ni]);
                }
            }
        }
        __syncthreads();
    }

    const int mLane = lane >> 2;
    const int nLane = (lane & 3) * 2;
    #pragma unroll
    for (int mi = 0; mi < 4; mi++) {
        #pragma unroll
        for (int half = 0; half < 2; half++) {
            int m = mBase + warpM + mi * 16 + mLane + half * 8;
            int orow = m;
            if (flags & F_REMAP) {
                if (m >= MBc) continue;
                orow = (m & 31) * TDc + (m >> 5);
            }
            #pragma unroll
            for (int ni = 0; ni < 4; ni++) {
                int n = nBase + warpN + ni * 8 + nLane;
                float vx = acc[mi][ni][half * 2 + 0] + bias[n];
                float vy = acc[mi][ni][half * 2 + 1] + bias[n + 1];
                if (flags & F_RELU) { vx = fmaxf(vx, 0.f); vy = fmaxf(vy, 0.f); }
                if (flags & F_SPLIT) {
                    size_t o = (size_t)orow * ldc + n;
                    __nv_bfloat16 hx = __float2bfloat16(vx), hy = __float2bfloat16(vy);
                    Chi[o] = hx; Chi[o+1] = hy;
                    Clo[o]   = __float2bfloat16(vx - __bfloat162float(hx));
                    Clo[o+1] = __float2bfloat16(vy - __bfloat162float(hy));
                } else {
                    *(float2*)(Cf + (size_t)orow * ldc + n) = make_float2(vx, vy);
                }
            }
        }
    }
}

// =============== 128x256 split-bf16 GEMM for the logits (512 thr, 25% less cp.async) =========
#define ATILE2 10240                 // 128*SLDA*2
#define BTILE2 20480                 // 256*SLDA*2
#define STAGE2 (2*ATILE2 + 2*BTILE2) // 61440
#define GEMM2_SMEM (2*STAGE2)        // 122880

__global__ __launch_bounds__(512) void gemm_bf16_w256(
    int K,
    const __nv_bfloat16* __restrict__ Ah, const __nv_bfloat16* __restrict__ Al,
    const __nv_bfloat16* __restrict__ Bh, const __nv_bfloat16* __restrict__ Bl,
    const float* __restrict__ bias, float* __restrict__ Cf, int ldc)
{
    extern __shared__ char smem[];
    const uint32_t smem_base = smem_u32(smem);
    const int tid = threadIdx.x, wid = tid >> 5, lane = tid & 31;
    const int nBase = blockIdx.x * 256;
    const int mBase = blockIdx.y * 128;
    const int warpM = (wid & 1) * 64;     // 2 M-warps
    const int warpN = (wid >> 1) * 32;    // 8 N-warps -> 256 cols

    const __nv_bfloat16* gAh = Ah + (size_t)mBase * K;
    const __nv_bfloat16* gAl = Al + (size_t)mBase * K;
    const __nv_bfloat16* gBh = Bh + (size_t)nBase * K;
    const __nv_bfloat16* gBl = Bl + (size_t)nBase * K;

    // A tiles: 512 segs each (tid covers); B tiles: 1024 segs each (tid, tid+512)
    const int aR = tid >> 2, aS = tid & 3;
    const int b0R = tid >> 2, b0S = tid & 3;
    const int b1R = (tid + 512) >> 2, b1S = ((tid + 512) & 3);

    auto prefetch = [&](int st, int kc) {
        uint32_t sb = smem_base + st * STAGE2;
        CP16(sb + (uint32_t)(aR * SLDA + aS * 8) * 2,            gAh + (size_t)aR * K + kc + aS * 8);
        CP16(sb + ATILE2 + (uint32_t)(aR * SLDA + aS * 8) * 2,   gAl + (size_t)aR * K + kc + aS * 8);
        uint32_t bb = sb + 2 * ATILE2;
        CP16(bb + (uint32_t)(b0R * SLDA + b0S * 8) * 2,          gBh + (size_t)b0R * K + kc + b0S * 8);
        CP16(bb + (uint32_t)(b1R * SLDA + b1S * 8) * 2,          gBh + (size_t)b1R * K + kc + b1S * 8);
        CP16(bb + BTILE2 + (uint32_t)(b0R * SLDA + b0S * 8) * 2, gBl + (size_t)b0R * K + kc + b0S * 8);
        CP16(bb + BTILE2 + (uint32_t)(b1R * SLDA + b1S * 8) * 2, gBl + (size_t)b1R * K + kc + b1S * 8);
    };

    float acc[4][4][4];
    #pragma unroll
    for (int i = 0; i < 4; i++)
        #pragma unroll
        for (int j = 0; j < 4; j++)
            #pragma unroll
            for (int e = 0; e < 4; e++) acc[i][j][e] = 0.f;

    const int aRow = (lane & 15), aK = (lane >> 4) * 8;
    const int bRow = ((lane >> 4) << 3) + (lane & 7), bK = ((lane >> 3) & 1) * 8;

    const int nch = K >> 5;
    prefetch(0, 0);
    CP_COMMIT();

    for (int c = 0; c < nch; c++) {
        if (c + 1 < nch) prefetch((c + 1) & 1, (c + 1) << 5);
        CP_COMMIT();
        CP_WAIT1();
        __syncthreads();

        const uint32_t stb = smem_base + (c & 1) * STAGE2;
        const uint32_t bAh = stb, bAl = stb + ATILE2;
        const uint32_t bBh = stb + 2*ATILE2, bBl = bBh + BTILE2;

        #pragma unroll
        for (int ks = 0; ks < 2; ks++) {
            const int kb = ks * 16;
            uint32_t fbh[4][2], fbl[4][2];
            #pragma unroll
            for (int nt = 0; nt < 2; nt++) {
                uint32_t off = ((uint32_t)(warpN + nt * 16 + bRow) * SLDA + kb + bK) * 2;
                ldm4(fbh[nt*2][0], fbh[nt*2][1], fbh[nt*2+1][0], fbh[nt*2+1][1], bBh + off);
                ldm4(fbl[nt*2][0], fbl[nt*2][1], fbl[nt*2+1][0], fbl[nt*2+1][1], bBl + off);
            }
            #pragma unroll
            for (int mi = 0; mi < 4; mi++) {
                uint32_t fah[4], fal[4];
                uint32_t off = ((uint32_t)(warpM + mi * 16 + aRow) * SLDA + kb + aK) * 2;
                ldm4(fah[0], fah[1], fah[2], fah[3], bAh + off);
                ldm4(fal[0], fal[1], fal[2], fal[3], bAl + off);
                #pragma unroll
                for (int ni = 0; ni < 4; ni++) {
                    mma16816(acc[mi][ni], fah, fbh[ni]);
                    mma16816(acc[mi][ni], fah, fbl[ni]);
                    mma16816(acc[mi][ni], fal, fbh[ni]);
                }
            }
        }
        __syncthreads();
    }

    // epilogue: bias + row remap (always), guard m < MBc
    const int mLane = lane >> 2;
    const int nLane = (lane & 3) * 2;
    #pragma unroll
    for (int mi = 0; mi < 4; mi++) {
        #pragma unroll
        for (int half = 0; half < 2; half++) {
            int m = mBase + warpM + mi * 16 + mLane + half * 8;
            if (m >= MBc) continue;
            int orow = (m & 31) * TDc + (m >> 5);
            #pragma unroll
            for (int ni = 0; ni < 4; ni++) {
                int n = nBase + warpN + ni * 8 + nLane;
                float vx = acc[mi][ni][half * 2 + 0] + bias[n];
                float vy = acc[mi][ni][half * 2 + 1] + bias[n + 1];
                *(float2*)(Cf + (size_t)orow * ldc + n) = make_float2(vx, vy);
            }
        }
    }
}

// ---------------- shared helpers for recurrent kernels (R9 float4 versions) ----------------
__device__ __forceinline__ void gate3_chunk(
    const float (*hs)[132], int row, const float* pr, const float* pz, const float* pn,
    float& a0, float& a1, float& a2)
{
    #pragma unroll 8
    for (int k = 0; k < 128; k += 4) {
        float4 hv = *(const float4*)&hs[row][k];
        float4 w4;
        w4 = *(const float4*)&pr[k]; a0 += hv.x*w4.x + hv.y*w4.y + hv.z*w4.z + hv.w*w4.w;
        w4 = *(const float4*)&pz[k]; a1 += hv.x*w4.x + hv.y*w4.y + hv.z*w4.z + hv.w*w4.w;
        w4 = *(const float4*)&pn[k]; a2 += hv.x*w4.x + hv.y*w4.y + hv.z*w4.z + hv.w*w4.w;
    }
}
__device__ __forceinline__ void stage_tile(float (*hs)[132], const float* src, int kc, int nthr, int tid) {
    for (int i = tid; i < 1024; i += nthr) {
        int r = i >> 5, kk = (i & 31) << 2;
        *(float4*)&hs[r][kk] = *(const float4*)&src[(size_t)r*Hc + kc + kk];
    }
}

// =============== persistent encoder GRU layer: 128 blocks, 128 steps internal ===============
#define ENC_SMEM (49152 + 32*132*4)
__global__ __launch_bounds__(256) void enc_gru_persist(
    const float* __restrict__ gi, const float* __restrict__ WhhBase,
    const float* __restrict__ bhhBase, float* __restrict__ y, unsigned* bar)
{
    extern __shared__ char sm[];
    float* wsm = (float*)sm;                            // [3][8][512]
    float (*hs)[132] = (float(*)[132])(sm + 49152);
    const int tid = threadIdx.x, wid = tid >> 5, row = tid & 31;
    const int dir = blockIdx.x >> 6;
    const int jb  = blockIdx.x & 63;
    const int j   = jb * 8 + wid;
    const int dcol = dir * Hc;
    const float* Whh = WhhBase + (size_t)dir * G3 * Hc;
    const float* bhh = bhhBase + dir * G3;

    for (int i = tid; i < 3*8*512; i += 256) {
        int g = i >> 12, rem = i & 4095, w = rem >> 9, k = rem & 511;
        wsm[i] = Whh[(size_t)(g*Hc + jb*8 + w)*Hc + k];
    }
    const float b0 = bhh[j], b1 = bhh[Hc + j], b2 = bhh[2*Hc + j];
    __syncthreads();

    for (int s = 0; s < Lc; s++) {
        const int te = dir ? (Lc - 1 - s) : s;
        const int tprev = dir ? (te + 1) : (te - 1);
        const bool first = (s == 0);
        float ar = 0.f, az = 0.f, an = 0.f;
        for (int kc = 0; kc < Hc; kc += 128) {
            for (int i = tid; i < 1024; i += 256) {
                int r = i >> 5, kk = (i & 31) << 2;
                float4 v = make_float4(0,0,0,0);
                if (!first) v = *(const float4*)&y[((size_t)tprev*Bc + r)*(2*Hc) + dcol + kc + kk];
                *(float4*)&hs[r][kk] = v;
            }
            __syncthreads();
            gate3_chunk(hs, row, wsm + wid*512 + kc, wsm + 4096 + wid*512 + kc,
                        wsm + 8192 + wid*512 + kc, ar, az, an);
            __syncthreads();
        }
        const float* gp = gi + ((size_t)te*Bc + row) * (2*G3) + dir * G3;
        float rg = 1.f / (1.f + __expf(-(gp[j]      + ar + b0)));
        float zg = 1.f / (1.f + __expf(-(gp[Hc + j] + az + b1)));
        float ng = tanhf(gp[2*Hc + j] + rg * (an + b2));
        float hp = first ? 0.f : y[((size_t)tprev*Bc + row)*(2*Hc) + dcol + j];
        y[((size_t)te*Bc + row)*(2*Hc) + dcol + j] = (1.f - zg)*ng + zg*hp;
        if (s < Lc - 1) gbar(bar, 128u * (unsigned)(s + 1));
    }
}

// ---------------- enc_out = y1[:, :H] + y1[:, H:] ----------------
__global__ void combine_enc(const float* __restrict__ y1, float* __restrict__ eo)
{
    int i = blockIdx.x;
    int h = threadIdx.x * 4;
    float4 a = *(const float4*)&y1[(size_t)i*2*Hc + h];
    float4 b = *(const float4*)&y1[(size_t)i*2*Hc + Hc + h];
    *(float4*)&eo[(size_t)i*Hc + h] = make_float4(a.x+b.x, a.y+b.y, a.z+b.z, a.w+b.w);
}

// =============== persistent decoder: 128 blocks x 128 thr, 63 steps x 4 phases ===============
#define DEC_SMEM (4*24576 + 8192 + 32*132*4 + (512+128+4)*4)
__global__ __launch_bounds__(128) void dec_persist(
    const float* __restrict__ dWih0, const float* __restrict__ dWhh0,
    const float* __restrict__ bhh0,
    const float* __restrict__ dWih1, const float* __restrict__ dWhh1,
    const float* __restrict__ bih1, const float* __restrict__ bhh1,
    const float* __restrict__ Wd, const float* __restrict__ bd,
    const float* __restrict__ dpre,
    const float* __restrict__ encq, const float* __restrict__ encout,
    float* __restrict__ h0b, float* __restrict__ h1b, float* __restrict__ ctxb,
    float* __restrict__ qb, float* __restrict__ feat, unsigned* bar)
{
    extern __shared__ char sm[];
    float* wx0 = (float*)sm;                 // each [3][4][512] = 6144 floats
    float* wh0 = wx0 + 6144;
    float* wx1 = wh0 + 6144;
    float* wh1 = wx1 + 6144;
    float* wd  = wh1 + 6144;                 // [4][512]
    float (*hs)[132] = (float(*)[132])(wd + 2048);
    float* qs   = (float*)hs + 32*132;       // 512
    float* es   = qs + 512;                  // 128
    float* ssum = es + 128;                  // 4

    const int tid = threadIdx.x, w = tid >> 5, lane = tid & 31, row = lane;
    const int blk = blockIdx.x;
    const int j = blk * 4 + w;

    for (int i = tid; i < 6144; i += 128) {
        int g = i / 2048, rem = i - g*2048, ww = rem >> 9, k = rem & 511;
        int r0 = g*Hc + blk*4 + ww;
        wx0[i] = dWih0[(size_t)r0*(Ec + Hc) + Ec + k];
        wh0[i] = dWhh0[(size_t)r0*Hc + k];
        wx1[i] = dWih1[(size_t)r0*Hc + k];
        wh1[i] = dWhh1[(size_t)r0*Hc + k];
    }
    for (int i = tid; i < 2048; i += 128)
        wd[i] = Wd[(size_t)(blk*4 + (i >> 9))*Hc + (i & 511)];
    const float bh0r = bhh0[j], bh0z = bhh0[Hc+j], bh0n = bhh0[2*Hc+j];
    const float bi1r = bih1[j], bi1z = bih1[Hc+j], bi1n = bih1[2*Hc+j];
    const float bh1r = bhh1[j], bh1z = bhh1[Hc+j], bh1n = bhh1[2*Hc+j];
    const float bdj = bd[j];
    __syncthreads();

    unsigned bi = 0;
    for (int t = 0; t < TDc; t++) {
        const int r = t & 1, wix = 1 - r;
        const float* ctxp = ctxb + (size_t)r*Bc*Hc;
        const float* h0p  = h0b  + (size_t)r*Bc*Hc;
        float*       h0n  = h0b  + (size_t)wix*Bc*Hc;
        const float* h1p  = h1b  + (size_t)r*Bc*Hc;
        float*       h1n  = h1b  + (size_t)wix*Bc*Hc;

        // ---- phase 1: cell0 (x=ctx, h=h0) ----
        {
            float air=0.f, aiz=0.f, ain=0.f, ahr=0.f, ahz=0.f, ahn=0.f;
            for (int kc = 0; kc < Hc; kc += 128) {
                stage_tile(hs, ctxp, kc, 128, tid);
                __syncthreads();
                gate3_chunk(hs, row, wx0 + w*512 + kc, wx0 + 2048 + w*512 + kc,
                            wx0 + 4096 + w*512 + kc, air, aiz, ain);
                __syncthreads();
            }
            for (int kc = 0; kc < Hc; kc += 128) {
                stage_tile(hs, h0p, kc, 128, tid);
                __syncthreads();
                gate3_chunk(hs, row, wh0 + w*512 + kc, wh0 + 2048 + w*512 + kc,
                            wh0 + 4096 + w*512 + kc, ahr, ahz, ahn);
                __syncthreads();
            }
            const float* pre = dpre + ((size_t)t*Bc + row)*G3;
            float rg = 1.f / (1.f + __expf(-(air + pre[j]      + ahr + bh0r)));
            float zg = 1.f / (1.f + __expf(-(aiz + pre[Hc+j]   + ahz + bh0z)));
            float ng = tanhf(ain + pre[2*Hc+j] + rg * (ahn + bh0n));
            h0n[(size_t)row*Hc + j] = (1.f - zg)*ng + zg*h0p[(size_t)row*Hc + j];
        }
        gbar(bar, 128u * (++bi));

        // ---- phase 2: cell1 (x=h0n, h=h1) ----
        {
            float air=0.f, aiz=0.f, ain=0.f, ahr=0.f, ahz=0.f, ahn=0.f;
            for (int kc = 0; kc < Hc; kc += 128) {
                stage_tile(hs, h0n, kc, 128, tid);
                __syncthreads();
                gate3_chunk(hs, row, wx1 + w*512 + kc, wx1 + 2048 + w*512 + kc,
                            wx1 + 4096 + w*512 + kc, air, aiz, ain);
                __syncthreads();
            }
            for (int kc = 0; kc < Hc; kc += 128) {
                stage_tile(hs, h1p, kc, 128, tid);
                __syncthreads();
                gate3_chunk(hs, row, wh1 + w*512 + kc, wh1 + 2048 + w*512 + kc,
                            wh1 + 4096 + w*512 + kc, ahr, ahz, ahn);
                __syncthreads();
            }
            float rg = 1.f / (1.f + __expf(-(air + bi1r + ahr + bh1r)));
            float zg = 1.f / (1.f + __expf(-(aiz + bi1z + ahz + bh1z)));
            float ng = tanhf(ain + bi1n + rg * (ahn + bh1n));
            h1n[(size_t)row*Hc + j] = (1.f - zg)*ng + zg*h1p[(size_t)row*Hc + j];
        }
        gbar(bar, 128u * (++bi));

        // ---- phase 3: q = h1n @ Wd^T + bd ----
        {
            float acc = 0.f;
            for (int kc = 0; kc < Hc; kc += 128) {
                stage_tile(hs, h1n, kc, 128, tid);
                __syncthreads();
                const float* wj = wd + w*512 + kc;
                #pragma unroll 8
                for (int k = 0; k < 128; k += 4) {
                    float4 hv = *(const float4*)&hs[row][k];
                    float4 w4 = *(const float4*)&wj[k];
                    acc += hv.x*w4.x + hv.y*w4.y + hv.z*w4.z + hv.w*w4.w;
                }
                __syncthreads();
            }
            qb[(size_t)row*Hc + j] = acc + bdj;
        }
        gbar(bar, 128u * (++bi));

        // ---- phase 4: attention + feat (blocks 0..31, b = blk) ----
        if (blk < 32) {
            const int b = blk;
            qs[tid]       = qb[(size_t)b*Hc + tid];
            qs[tid + 128] = qb[(size_t)b*Hc + tid + 128];
            qs[tid + 256] = qb[(size_t)b*Hc + tid + 256];
            qs[tid + 384] = qb[(size_t)b*Hc + tid + 384];
            __syncthreads();
            for (int l = w; l < Lc; l += 4) {
                const float* eqr = encq + ((size_t)l*Bc + b) * Ac;
                float s = 0.f;
                #pragma unroll
                for (int qk = 0; qk < 4; qk++) {
                    int k = qk*128 + lane*4;
                    float4 a = *(const float4*)&eqr[k];
                    float4 c = *(const float4*)&qs[k];
                    s += a.x*c.x + a.y*c.y + a.z*c.z + a.w*c.w;
                }
                #pragma unroll
                for (int off = 16; off; off >>= 1) s += __shfl_xor_sync(0xffffffffu, s, off);
                if (lane == 0) es[l] = __expf(tanhf(s));
            }
            __syncthreads();
            {
                float v = es[tid];
                #pragma unroll
                for (int off = 16; off; off >>= 1) v += __shfl_xor_sync(0xffffffffu, v, off);
                if (lane == 0) ssum[w] = v;
            }
            __syncthreads();
            float inv = 1.f / (ssum[0] + ssum[1] + ssum[2] + ssum[3]);
            float a0=0.f, a1=0.f, a2=0.f, a3=0.f;
            for (int l = 0; l < Lc; l++) {
                float wl = es[l];
                const float* eor = encout + ((size_t)l*Bc + b) * Hc;
                a0 += wl*eor[tid]; a1 += wl*eor[tid+128]; a2 += wl*eor[tid+256]; a3 += wl*eor[tid+384];
            }
            a0 *= inv; a1 *= inv; a2 *= inv; a3 *= inv;
            float* cx = ctxb + (size_t)wix*Bc*Hc + (size_t)b*Hc;
            cx[tid]=a0; cx[tid+128]=a1; cx[tid+256]=a2; cx[tid+384]=a3;
            float* fp = feat + ((size_t)t*Bc + b) * 2*Hc;
            const float* h1r = h1n + (size_t)b*Hc;
            fp[tid]=h1r[tid]; fp[tid+128]=h1r[tid+128]; fp[tid+256]=h1r[tid+256]; fp[tid+384]=h1r[tid+384];
            fp[Hc+tid]=a0; fp[Hc+tid+128]=a1; fp[Hc+tid+256]=a2; fp[Hc+tid+384]=a3;
            __syncthreads();
        }
        ++bi;
        if (t < TDc - 1) gbar(bar, 128u * bi);
    }
}

// ================================================================================
extern "C" void kernel_launch(void* const* d_in, const int* in_sizes, int n_in,
                              void* d_out, int out_size)
{
    const int*   src_tokens = (const int*)  d_in[0];
    const int*   trgt_seq   = (const int*)  d_in[1];
    const float* enc_embed  = (const float*)d_in[3];
    const float* enc_Wih0   = (const float*)d_in[4];
    const float* enc_Whh0   = (const float*)d_in[5];
    const float* enc_bih0   = (const float*)d_in[6];
    const float* enc_bhh0   = (const float*)d_in[7];
    const float* enc_Wih1   = (const float*)d_in[8];
    const float* enc_Whh1   = (const float*)d_in[9];
    const float* enc_bih1   = (const float*)d_in[10];
    const float* enc_bhh1   = (const float*)d_in[11];
    const float* dec_embed  = (const float*)d_in[12];
    const float* dec_Wih0   = (const float*)d_in[13];
    const float* dec_Whh0   = (const float*)d_in[14];
    const float* dec_bih0   = (const float*)d_in[15];
    const float* dec_bhh0   = (const float*)d_in[16];
    const float* dec_Wih1   = (const float*)d_in[17];
    const float* dec_Whh1   = (const float*)d_in[18];
    const float* dec_bih1   = (const float*)d_in[19];
    const float* dec_bhh1   = (const float*)d_in[20];
    const float* attn_We    = (const float*)d_in[21];
    const float* attn_be    = (const float*)d_in[22];
    const float* attn_Wd    = (const float*)d_in[23];
    const float* attn_bd    = (const float*)d_in[24];
    const float* mlp_W1     = (const float*)d_in[25];
    const float* mlp_b1     = (const float*)d_in[26];
    const float* mlp_W2     = (const float*)d_in[27];
    const float* mlp_b2     = (const float*)d_in[28];

    float *emb, *decemb, *gi, *y0, *y1, *eo, *eq, *dpre, *h0b, *h1b, *ctxb, *qb, *feat;
    unsigned* bars;
    __nv_bfloat16 *Ah, *Al, *Wh, *Wl, *Bh, *Bl;
    cudaGetSymbolAddress((void**)&emb,    d_emb);
    cudaGetSymbolAddress((void**)&decemb, d_decemb);
    cudaGetSymbolAddress((void**)&gi,     d_gi);
    cudaGetSymbolAddress((void**)&y0,     d_y0);
    cudaGetSymbolAddress((void**)&y1,     d_y1);
    cudaGetSymbolAddress((void**)&eo,     d_eo);
    cudaGetSymbolAddress((void**)&eq,     d_eq);
    cudaGetSymbolAddress((void**)&dpre,   d_dpre);
    cudaGetSymbolAddress((void**)&h0b,    d_h0b);
    cudaGetSymbolAddress((void**)&h1b,    d_h1b);
    cudaGetSymbolAddress((void**)&ctxb,   d_ctxb);
    cudaGetSymbolAddress((void**)&qb,     d_qb);
    cudaGetSymbolAddress((void**)&feat,   d_feat);
    cudaGetSymbolAddress((void**)&bars,   d_bars);
    cudaGetSymbolAddress((void**)&Ah,     d_Ah);
    cudaGetSymbolAddress((void**)&Al,     d_Al);
    cudaGetSymbolAddress((void**)&Wh,     d_Wh);
    cudaGetSymbolAddress((void**)&Wl,     d_Wl);
    cudaGetSymbolAddress((void**)&Bh,     d_Bh);
    cudaGetSymbolAddress((void**)&Bl,     d_Bl);

    cudaFuncSetAttribute(gemm_bf16,       cudaFuncAttributeMaxDynamicSharedMemorySize, GEMM_SMEM);
    cudaFuncSetAttribute(gemm_bf16_w256,  cudaFuncAttributeMaxDynamicSharedMemorySize, GEMM2_SMEM);
    cudaFuncSetAttribute(enc_gru_persist, cudaFuncAttributeMaxDynamicSharedMemorySize, ENC_SMEM);
    cudaFuncSetAttribute(dec_persist,     cudaFuncAttributeMaxDynamicSharedMemorySize, DEC_SMEM);

    cudaMemsetAsync(bars, 0, 4*sizeof(unsigned));
    cudaMemsetAsync(h0b,  0, Bc*Hc*sizeof(float));
    cudaMemsetAsync(h1b,  0, Bc*Hc*sizeof(float));
    cudaMemsetAsync(ctxb, 0, Bc*Hc*sizeof(float));

    // embeddings
    gather_rows<<<Lc*Bc, 128>>>(src_tokens, enc_embed, emb, 0);
    gather_rows<<<MBc,   128>>>(trgt_seq,   dec_embed, decemb, 1);

    // mlp_W2 conversion (vectorized)
    { long n = (long)Vc * 1024; conv_split4<<<(unsigned)(n/1024), 256>>>(mlp_W2, Bh, Bl, n, n); }

    // ===== encoder layer0 pre + persistent recurrence =====
    { long n = (long)Lc*Bc*Ec;  conv_split4<<<(unsigned)(n/1024), 256>>>(emb, Ah, Al, n, n); }
    { long n = (long)2*G3*Ec;   conv_split4<<<(unsigned)(n/1024), 256>>>(enc_Wih0, Wh, Wl, n, n); }
    gemm_bf16<<<dim3(2*G3/128, Lc*Bc/128), 256, GEMM_SMEM>>>(
        Ec, Ah, Al, Wh, Wl, enc_bih0, gi, nullptr, nullptr, 2*G3, 0);
    enc_gru_persist<<<128, 256, ENC_SMEM>>>(gi, enc_Whh0, enc_bhh0, y0, bars + 0);

    // ===== encoder layer1 =====
    { long n = (long)Lc*Bc*2*Hc; conv_split4<<<(unsigned)(n/1024), 256>>>(y0, Ah, Al, n, n); }
    { long n = (long)2*G3*2*Hc;  conv_split4<<<(unsigned)(n/1024), 256>>>(enc_Wih1, Wh, Wl, n, n); }
    gemm_bf16<<<dim3(2*G3/128, Lc*Bc/128), 256, GEMM_SMEM>>>(
        2*Hc, Ah, Al, Wh, Wl, enc_bih1, gi, nullptr, nullptr, 2*G3, 0);
    enc_gru_persist<<<128, 256, ENC_SMEM>>>(gi, enc_Whh1, enc_bhh1, y1, bars + 1);

    combine_enc<<<Lc*Bc, 128>>>(y1, eo);

    // ===== enc_q =====
    { long n = (long)Lc*Bc*Hc; conv_split4<<<(unsigned)(n/1024), 256>>>(eo, Ah, Al, n, n); }
    { long n = (long)Ac*Hc;    conv_split4<<<(unsigned)(n/1024), 256>>>(attn_We, Wh, Wl, n, n); }
    gemm_bf16<<<dim3(Ac/128, Lc*Bc/128), 256, GEMM_SMEM>>>(
        Hc, Ah, Al, Wh, Wl, attn_be, eq, nullptr, nullptr, Ac, 0);

    // ===== decoder pre =====
    { long nv = (long)MBc*Ec, nt = (long)MPAD*Ec;
      conv_split4<<<(unsigned)(nt/1024), 256>>>(decemb, Ah, Al, nv, nt); }
    { long n = (long)G3*Ec;
      conv_split2d4<<<(unsigned)(n/1024), 256>>>(dec_Wih0, Ec + Hc, G3, Ec, Wh, Wl); }
    gemm_bf16<<<dim3(G3/128, MPAD/128), 256, GEMM_SMEM>>>(
        Ec, Ah, Al, Wh, Wl, dec_bih0, dpre, nullptr, nullptr, G3, 0);

    // ===== persistent decoder (63 steps, 4 phases each) =====
    dec_persist<<<128, 128, DEC_SMEM>>>(
        dec_Wih0, dec_Whh0, dec_bhh0,
        dec_Wih1, dec_Whh1, dec_bih1, dec_bhh1,
        attn_Wd, attn_bd, dpre, eq, eo,
        h0b, h1b, ctxb, qb, feat, bars + 2);

    // ===== MLP1 (split-bf16 out) =====
    { long nv = (long)MBc*2*Hc, nt = (long)MPAD*2*Hc;
      conv_split4<<<(unsigned)(nt/1024), 256>>>(feat, Ah, Al, nv, nt); }
    { long n = (long)2*Hc*2*Hc; conv_split4<<<(unsigned)(n/1024), 256>>>(mlp_W1, Wh, Wl, n, n); }
    __nv_bfloat16* Ah2 = Ah + (size_t)MPAD * 1024;
    __nv_bfloat16* Al2 = Al + (size_t)MPAD * 1024;
    gemm_bf16<<<dim3(2*Hc/128, MPAD/128), 256, GEMM_SMEM>>>(
        2*Hc, Ah, Al, Wh, Wl, mlp_b1, nullptr, Ah2, Al2, 2*Hc, F_RELU | F_SPLIT);

    // ===== MLP2 logits: 128x256 tiles, 25% fewer cp.async ops =====
    gemm_bf16_w256<<<dim3(Vc/256, MPAD/128), 512, GEMM2_SMEM>>>(
        2*Hc, Ah2, Al2, Bh, Bl, mlp_b2, (float*)d_out, Vc);
}

// round 17
// speedup vs baseline: 1.4149x; 1.3276x over previous
#include <cuda_runtime.h>
#include <cuda_bf16.h>
#include <cstdint>
#include <math.h>

#define Lc 128
#define Bc 32
#define Tc 64
#define TDc 63
#define Ec 512
#define Hc 512
#define Ac 512
#define Vc 32000
#define G3 1536
#define MBc (TDc*Bc)   // 2016
#define MPAD 2048
#define HSW 516        // hs row stride in floats (516 mod 32 = 4 -> conflict-free per ldmatrix phase)

// ---------------- scratch ----------------
__device__ float d_emb   [Lc*Bc*Ec];
__device__ float d_decemb[MBc*Ec];
__device__ float d_gi    [Lc*Bc*2*G3];
__device__ float d_y0    [Lc*Bc*2*Hc];
__device__ float d_y1    [Lc*Bc*2*Hc];
__device__ float d_eo    [Lc*Bc*Hc];
__device__ float d_eq    [Lc*Bc*Ac];
__device__ float d_dpre  [MPAD*G3];
__device__ float d_h0b   [2*Bc*Hc];
__device__ float d_h1b   [2*Bc*Hc];
__device__ float d_ctxb  [2*Bc*Hc];
__device__ float d_qb    [Bc*Ac];
__device__ float d_feat  [MBc*2*Hc];
__device__ unsigned d_bars[8];
// bf16 split operand buffers
__device__ __nv_bfloat16 d_Ah[4096*1024];
__device__ __nv_bfloat16 d_Al[4096*1024];
__device__ __nv_bfloat16 d_Wh[3072*1024];
__device__ __nv_bfloat16 d_Wl[3072*1024];
__device__ __nv_bfloat16 d_Bh[(size_t)Vc*1024];
__device__ __nv_bfloat16 d_Bl[(size_t)Vc*1024];

// ---------------- grid barrier (release/acquire; bar.sync provides the HB edge) ---------------
__device__ __forceinline__ void gbar(unsigned* cnt, unsigned target) {
    __syncthreads();
    if (threadIdx.x == 0) {
        unsigned v;
        asm volatile("red.release.gpu.global.add.u32 [%0], 1;" :: "l"(cnt) : "memory");
        do {
            asm volatile("ld.acquire.gpu.global.u32 %0, [%1];" : "=r"(v) : "l"(cnt) : "memory");
        } while (v < target);
    }
    __syncthreads();
}

// ---------------- embedding gathers ----------------
__global__ void gather_rows(const int* __restrict__ tok, const float* __restrict__ tab,
                            float* __restrict__ out, int mode)
{
    int row = blockIdx.x;
    int idx;
    if (mode == 0) idx = tok[row];
    else { int t = row >> 5, b = row & 31; idx = tok[b*Tc + t]; }
    const float4* src = (const float4*)(tab + (size_t)idx * Ec);
    float4* dst = (float4*)(out + (size_t)row * Ec);
    dst[threadIdx.x] = src[threadIdx.x];
}

// ---------------- fp32 -> split bf16, 4-wide vectorized ----------------
__device__ __forceinline__ void split1(float v, __nv_bfloat16& h, __nv_bfloat16& l) {
    h = __float2bfloat16(v);
    l = __float2bfloat16(v - __bfloat162float(h));
}
__global__ void conv_split4(const float* __restrict__ in, __nv_bfloat16* __restrict__ hi,
                            __nv_bfloat16* __restrict__ lo, long n_valid, long n_total)
{
    long i = ((long)blockIdx.x * blockDim.x + threadIdx.x) * 4;
    if (i >= n_total) return;
    float4 v = (i + 3 < n_valid) ? *(const float4*)(in + i) : make_float4(
        (i   < n_valid) ? in[i]   : 0.f, (i+1 < n_valid) ? in[i+1] : 0.f,
        (i+2 < n_valid) ? in[i+2] : 0.f, (i+3 < n_valid) ? in[i+3] : 0.f);
    __nv_bfloat16 h[4], l[4];
    split1(v.x, h[0], l[0]); split1(v.y, h[1], l[1]);
    split1(v.z, h[2], l[2]); split1(v.w, h[3], l[3]);
    *(ulonglong1*)(hi + i) = *(ulonglong1*)h;
    *(ulonglong1*)(lo + i) = *(ulonglong1*)l;
}
__global__ void conv_split2d4(const float* __restrict__ in, int ld, int rows, int cols,
                              __nv_bfloat16* __restrict__ hi, __nv_bfloat16* __restrict__ lo)
{
    long i = ((long)blockIdx.x * blockDim.x + threadIdx.x) * 4;
    if (i >= (long)rows * cols) return;
    int r = (int)(i / cols), c = (int)(i % cols);
    float4 v = *(const float4*)(in + (size_t)r * ld + c);
    __nv_bfloat16 h[4], l[4];
    split1(v.x, h[0], l[0]); split1(v.y, h[1], l[1]);
    split1(v.z, h[2], l[2]); split1(v.w, h[3], l[3]);
    *(ulonglong1*)(hi + i) = *(ulonglong1*)h;
    *(ulonglong1*)(lo + i) = *(ulonglong1*)l;
}

// =============== generic split-bf16 tensor GEMM (x = N-tiles, y = M-tiles) ===============
#define F_RELU  1
#define F_REMAP 2
#define F_SPLIT 4
#define SLDA 40
#define TILEB (128*SLDA*2)
#define STAGEB (4*TILEB)
#define GEMM_SMEM (2*STAGEB)

__device__ __forceinline__ uint32_t smem_u32(const void* p) {
    uint32_t a;
    asm("{ .reg .u64 t; cvta.to.shared.u64 t, %1; cvt.u32.u64 %0, t; }" : "=r"(a) : "l"(p));
    return a;
}
__device__ __forceinline__ void ldm4(uint32_t& r0, uint32_t& r1, uint32_t& r2, uint32_t& r3, uint32_t a) {
    asm volatile("ldmatrix.sync.aligned.m8n8.x4.shared.b16 {%0,%1,%2,%3}, [%4];"
                 : "=r"(r0), "=r"(r1), "=r"(r2), "=r"(r3) : "r"(a));
}
__device__ __forceinline__ void mma16816(float* c, const uint32_t* a, const uint32_t* b) {
    asm volatile("mma.sync.aligned.m16n8k16.row.col.f32.bf16.bf16.f32 "
                 "{%0,%1,%2,%3},{%4,%5,%6,%7},{%8,%9},{%0,%1,%2,%3};"
                 : "+f"(c[0]), "+f"(c[1]), "+f"(c[2]), "+f"(c[3])
                 : "r"(a[0]), "r"(a[1]), "r"(a[2]), "r"(a[3]), "r"(b[0]), "r"(b[1]));
}
#define CP16(dst, src) asm volatile("cp.async.cg.shared.global [%0], [%1], 16;" :: "r"(dst), "l"(src))
#define CP_COMMIT()    asm volatile("cp.async.commit_group;" ::: "memory")
#define CP_WAIT1()     asm volatile("cp.async.wait_group 1;" ::: "memory")

__global__ __launch_bounds__(256) void gemm_bf16(
    int K,
    const __nv_bfloat16* __restrict__ Ah, const __nv_bfloat16* __restrict__ Al,
    const __nv_bfloat16* __restrict__ Bh, const __nv_bfloat16* __restrict__ Bl,
    const float* __restrict__ bias,
    float* __restrict__ Cf, __nv_bfloat16* __restrict__ Chi, __nv_bfloat16* __restrict__ Clo,
    int ldc, int flags)
{
    extern __shared__ char smem[];
    const uint32_t smem_base = smem_u32(smem);
    const int tid = threadIdx.x, wid = tid >> 5, lane = tid & 31;
    const int nBase = blockIdx.x * 128;
    const int mBase = blockIdx.y * 128;
    const int warpM = (wid & 1) * 64;
    const int warpN = (wid >> 1) * 32;

    const __nv_bfloat16* g[4] = {
        Ah + (size_t)mBase * K, Al + (size_t)mBase * K,
        Bh + (size_t)nBase * K, Bl + (size_t)nBase * K };

    const int lRow0 = tid >> 2, lSc0 = (tid & 3);
    const int lRow1 = (tid + 256) >> 2, lSc1 = ((tid + 256) & 3);

    auto prefetch = [&](int st, int kc) {
        #pragma unroll
        for (int op = 0; op < 4; op++) {
            uint32_t sb = smem_base + st * STAGEB + op * TILEB;
            CP16(sb + (uint32_t)(lRow0 * SLDA + lSc0 * 8) * 2, g[op] + (size_t)lRow0 * K + kc + lSc0 * 8);
            CP16(sb + (uint32_t)(lRow1 * SLDA + lSc1 * 8) * 2, g[op] + (size_t)lRow1 * K + kc + lSc1 * 8);
        }
    };

    float acc[4][4][4];
    #pragma unroll
    for (int i = 0; i < 4; i++)
        #pragma unroll
        for (int j = 0; j < 4; j++)
            #pragma unroll
            for (int e = 0; e < 4; e++) acc[i][j][e] = 0.f;

    const int aRow = (lane & 15), aK = (lane >> 4) * 8;
    const int bRow = ((lane >> 4) << 3) + (lane & 7), bK = ((lane >> 3) & 1) * 8;

    const int nch = K >> 5;
    prefetch(0, 0);
    CP_COMMIT();

    for (int c = 0; c < nch; c++) {
        if (c + 1 < nch) prefetch((c + 1) & 1, (c + 1) << 5);
        CP_COMMIT();
        CP_WAIT1();
        __syncthreads();

        const uint32_t stb = smem_base + (c & 1) * STAGEB;
        const uint32_t bAh = stb, bAl = stb + TILEB, bBh = stb + 2*TILEB, bBl = stb + 3*TILEB;

        #pragma unroll
        for (int ks = 0; ks < 2; ks++) {
            const int kb = ks * 16;
            uint32_t fbh[4][2], fbl[4][2];
            #pragma unroll
            for (int nt = 0; nt < 2; nt++) {
                uint32_t off = ((uint32_t)(warpN + nt * 16 + bRow) * SLDA + kb + bK) * 2;
                ldm4(fbh[nt*2][0], fbh[nt*2][1], fbh[nt*2+1][0], fbh[nt*2+1][1], bBh + off);
                ldm4(fbl[nt*2][0], fbl[nt*2][1], fbl[nt*2+1][0], fbl[nt*2+1][1], bBl + off);
            }
            #pragma unroll
            for (int mi = 0; mi < 4; mi++) {
                uint32_t fah[4], fal[4];
                uint32_t off = ((uint32_t)(warpM + mi * 16 + aRow) * SLDA + kb + aK) * 2;
                ldm4(fah[0], fah[1], fah[2], fah[3], bAh + off);
                ldm4(fal[0], fal[1], fal[2], fal[3], bAl + off);
                #pragma unroll
                for (int ni = 0; ni < 4; ni++) {
                    mma16816(acc[mi][ni], fah, fbh[ni]);
                    mma16816(acc[mi][ni], fah, fbl[ni]);
                    mma16816(acc[mi][ni], fal, fbh[ni]);
                }
            }
        }
        __syncthreads();
    }

    const int mLane = lane >> 2;
    const int nLane = (lane & 3) * 2;
    #pragma unroll
    for (int mi = 0; mi < 4; mi++) {
        #pragma unroll
        for (int half = 0; half < 2; half++) {
            int m = mBase + warpM + mi * 16 + mLane + half * 8;
            int orow = m;
            if (flags & F_REMAP) {
                if (m >= MBc) continue;
                orow = (m & 31) * TDc + (m >> 5);
            }
            #pragma unroll
            for (int ni = 0; ni < 4; ni++) {
                int n = nBase + warpN + ni * 8 + nLane;
                float vx = acc[mi][ni][half * 2 + 0] + bias[n];
                float vy = acc[mi][ni][half * 2 + 1] + bias[n + 1];
                if (flags & F_RELU) { vx = fmaxf(vx, 0.f); vy = fmaxf(vy, 0.f); }
                if (flags & F_SPLIT) {
                    size_t o = (size_t)orow * ldc + n;
                    __nv_bfloat16 hx = __float2bfloat16(vx), hy = __float2bfloat16(vy);
                    Chi[o] = hx; Chi[o+1] = hy;
                    Clo[o]   = __float2bfloat16(vx - __bfloat162float(hx));
                    Clo[o+1] = __float2bfloat16(vy - __bfloat162float(hy));
                } else {
                    *(float2*)(Cf + (size_t)orow * ldc + n) = make_float2(vx, vy);
                }
            }
        }
    }
}

// =============== 128x256 split-bf16 GEMM for the logits ===============
#define ATILE2 10240
#define BTILE2 20480
#define STAGE2 (2*ATILE2 + 2*BTILE2)
#define GEMM2_SMEM (2*STAGE2)

__global__ __launch_bounds__(512) void gemm_bf16_w256(
    int K,
    const __nv_bfloat16* __restrict__ Ah, const __nv_bfloat16* __restrict__ Al,
    const __nv_bfloat16* __restrict__ Bh, const __nv_bfloat16* __restrict__ Bl,
    const float* __restrict__ bias, float* __restrict__ Cf, int ldc)
{
    extern __shared__ char smem[];
    const uint32_t smem_base = smem_u32(smem);
    const int tid = threadIdx.x, wid = tid >> 5, lane = tid & 31;
    const int nBase = blockIdx.x * 256;
    const int mBase = blockIdx.y * 128;
    const int warpM = (wid & 1) * 64;
    const int warpN = (wid >> 1) * 32;

    const __nv_bfloat16* gAh = Ah + (size_t)mBase * K;
    const __nv_bfloat16* gAl = Al + (size_t)mBase * K;
    const __nv_bfloat16* gBh = Bh + (size_t)nBase * K;
    const __nv_bfloat16* gBl = Bl + (size_t)nBase * K;

    const int aR = tid >> 2, aS = tid & 3;
    const int b0R = tid >> 2, b0S = tid & 3;
    const int b1R = (tid + 512) >> 2, b1S = ((tid + 512) & 3);

    auto prefetch = [&](int st, int kc) {
        uint32_t sb = smem_base + st * STAGE2;
        CP16(sb + (uint32_t)(aR * SLDA + aS * 8) * 2,            gAh + (size_t)aR * K + kc + aS * 8);
        CP16(sb + ATILE2 + (uint32_t)(aR * SLDA + aS * 8) * 2,   gAl + (size_t)aR * K + kc + aS * 8);
        uint32_t bb = sb + 2 * ATILE2;
        CP16(bb + (uint32_t)(b0R * SLDA + b0S * 8) * 2,          gBh + (size_t)b0R * K + kc + b0S * 8);
        CP16(bb + (uint32_t)(b1R * SLDA + b1S * 8) * 2,          gBh + (size_t)b1R * K + kc + b1S * 8);
        CP16(bb + BTILE2 + (uint32_t)(b0R * SLDA + b0S * 8) * 2, gBl + (size_t)b0R * K + kc + b0S * 8);
        CP16(bb + BTILE2 + (uint32_t)(b1R * SLDA + b1S * 8) * 2, gBl + (size_t)b1R * K + kc + b1S * 8);
    };

    float acc[4][4][4];
    #pragma unroll
    for (int i = 0; i < 4; i++)
        #pragma unroll
        for (int j = 0; j < 4; j++)
            #pragma unroll
            for (int e = 0; e < 4; e++) acc[i][j][e] = 0.f;

    const int aRow = (lane & 15), aK = (lane >> 4) * 8;
    const int bRow = ((lane >> 4) << 3) + (lane & 7), bK = ((lane >> 3) & 1) * 8;

    const int nch = K >> 5;
    prefetch(0, 0);
    CP_COMMIT();

    for (int c = 0; c < nch; c++) {
        if (c + 1 < nch) prefetch((c + 1) & 1, (c + 1) << 5);
        CP_COMMIT();
        CP_WAIT1();
        __syncthreads();

        const uint32_t stb = smem_base + (c & 1) * STAGE2;
        const uint32_t bAh = stb, bAl = stb + ATILE2;
        const uint32_t bBh = stb + 2*ATILE2, bBl = bBh + BTILE2;

        #pragma unroll
        for (int ks = 0; ks < 2; ks++) {
            const int kb = ks * 16;
            uint32_t fbh[4][2], fbl[4][2];
            #pragma unroll
            for (int nt = 0; nt < 2; nt++) {
                uint32_t off = ((uint32_t)(warpN + nt * 16 + bRow) * SLDA + kb + bK) * 2;
                ldm4(fbh[nt*2][0], fbh[nt*2][1], fbh[nt*2+1][0], fbh[nt*2+1][1], bBh + off);
                ldm4(fbl[nt*2][0], fbl[nt*2][1], fbl[nt*2+1][0], fbl[nt*2+1][1], bBl + off);
            }
            #pragma unroll
            for (int mi = 0; mi < 4; mi++) {
                uint32_t fah[4], fal[4];
                uint32_t off = ((uint32_t)(warpM + mi * 16 + aRow) * SLDA + kb + aK) * 2;
                ldm4(fah[0], fah[1], fah[2], fah[3], bAh + off);
                ldm4(fal[0], fal[1], fal[2], fal[3], bAl + off);
                #pragma unroll
                for (int ni = 0; ni < 4; ni++) {
                    mma16816(acc[mi][ni], fah, fbh[ni]);
                    mma16816(acc[mi][ni], fah, fbl[ni]);
                    mma16816(acc[mi][ni], fal, fbh[ni]);
                }
            }
        }
        __syncthreads();
    }

    const int mLane = lane >> 2;
    const int nLane = (lane & 3) * 2;
    #pragma unroll
    for (int mi = 0; mi < 4; mi++) {
        #pragma unroll
        for (int half = 0; half < 2; half++) {
            int m = mBase + warpM + mi * 16 + mLane + half * 8;
            if (m >= MBc) continue;
            int orow = (m & 31) * TDc + (m >> 5);
            #pragma unroll
            for (int ni = 0; ni < 4; ni++) {
                int n = nBase + warpN + ni * 8 + nLane;
                float vx = acc[mi][ni][half * 2 + 0] + bias[n];
                float vy = acc[mi][ni][half * 2 + 1] + bias[n + 1];
                *(float2*)(Cf + (size_t)orow * ldc + n) = make_float2(vx, vy);
            }
        }
    }
}

// ---------------- full-width recurrent helpers ----------------
__device__ __forceinline__ void gate3_full(
    const float* hrow, const float* pr, const float* pz, const float* pn,
    float& a0, float& a1, float& a2)
{
    #pragma unroll 8
    for (int k = 0; k < 512; k += 4) {
        float4 hv = *(const float4*)&hrow[k];
        float4 w4;
        w4 = *(const float4*)&pr[k]; a0 += hv.x*w4.x + hv.y*w4.y + hv.z*w4.z + hv.w*w4.w;
        w4 = *(const float4*)&pz[k]; a1 += hv.x*w4.x + hv.y*w4.y + hv.z*w4.z + hv.w*w4.w;
        w4 = *(const float4*)&pn[k]; a2 += hv.x*w4.x + hv.y*w4.y + hv.z*w4.z + hv.w*w4.w;
    }
}
// stage full 32x512 tile (src row stride Hc) into hs (row stride HSW)
__device__ __forceinline__ void stage_full(float* hs, const float* src, int nthr, int tid) {
    for (int i = tid; i < 4096; i += nthr) {
        int r = i >> 7, kk = (i & 127) << 2;
        *(float4*)&hs[r*HSW + kk] = *(const float4*)&src[(size_t)r*Hc + kk];
    }
}

// =============== persistent encoder GRU layer: 128 blocks (64/dir), per-dir barrier ==========
#define ENC_SMEM (49152 + 32*HSW*4)
__global__ __launch_bounds__(256) void enc_gru_persist(
    const float* __restrict__ gi, const float* __restrict__ WhhBase,
    const float* __restrict__ bhhBase, float* __restrict__ y, unsigned* barBase)
{
    extern __shared__ char sm[];
    float* wsm = (float*)sm;                            // [3][8][512]
    float* hs  = (float*)(sm + 49152);                  // [32][HSW]
    const int tid = threadIdx.x, wid = tid >> 5, row = tid & 31;
    const int dir = blockIdx.x >> 6;
    const int jb  = blockIdx.x & 63;
    const int j   = jb * 8 + wid;
    const int dcol = dir * Hc;
    const float* Whh = WhhBase + (size_t)dir * G3 * Hc;
    const float* bhh = bhhBase + dir * G3;
    unsigned* bar = barBase + dir;

    for (int i = tid; i < 3*8*512; i += 256) {
        int g = i >> 12, rem = i & 4095, w = rem >> 9, k = rem & 511;
        wsm[i] = Whh[(size_t)(g*Hc + jb*8 + w)*Hc + k];
    }
    const float b0 = bhh[j], b1 = bhh[Hc + j], b2 = bhh[2*Hc + j];
    __syncthreads();

    for (int s = 0; s < Lc; s++) {
        const int te = dir ? (Lc - 1 - s) : s;
        const int tprev = dir ? (te + 1) : (te - 1);
        const bool first = (s == 0);
        // stage full h_prev tile once (zero at s==0)
        for (int i = tid; i < 4096; i += 256) {
            int r = i >> 7, kk = (i & 127) << 2;
            float4 v = make_float4(0,0,0,0);
            if (!first) v = *(const float4*)&y[((size_t)tprev*Bc + r)*(2*Hc) + dcol + kk];
            *(float4*)&hs[r*HSW + kk] = v;
        }
        __syncthreads();
        float ar = 0.f, az = 0.f, an = 0.f;
        gate3_full(hs + row*HSW, wsm + wid*512, wsm + 4096 + wid*512, wsm + 8192 + wid*512,
                   ar, az, an);
        const float* gp = gi + ((size_t)te*Bc + row) * (2*G3) + dir * G3;
        float rg = 1.f / (1.f + __expf(-(gp[j]      + ar + b0)));
        float zg = 1.f / (1.f + __expf(-(gp[Hc + j] + az + b1)));
        float ng = tanhf(gp[2*Hc + j] + rg * (an + b2));
        float hp = first ? 0.f : hs[row*HSW + j];
        y[((size_t)te*Bc + row)*(2*Hc) + dcol + j] = (1.f - zg)*ng + zg*hp;
        if (s < Lc - 1) gbar(bar, 64u * (unsigned)(s + 1));
    }
}

// ---------------- enc_out = y1[:, :H] + y1[:, H:] ----------------
__global__ void combine_enc(const float* __restrict__ y1, float* __restrict__ eo)
{
    int i = blockIdx.x;
    int h = threadIdx.x * 4;
    float4 a = *(const float4*)&y1[(size_t)i*2*Hc + h];
    float4 b = *(const float4*)&y1[(size_t)i*2*Hc + Hc + h];
    *(float4*)&eo[(size_t)i*Hc + h] = make_float4(a.x+b.x, a.y+b.y, a.z+b.z, a.w+b.w);
}

// =============== persistent decoder: 128 blocks x 128 thr, 63 steps x 4 phases ===============
#define DEC_SMEM (4*24576 + 8192 + 32*HSW*4 + (512+128+4)*4)
__global__ __launch_bounds__(128) void dec_persist(
    const float* __restrict__ dWih0, const float* __restrict__ dWhh0,
    const float* __restrict__ bhh0,
    const float* __restrict__ dWih1, const float* __restrict__ dWhh1,
    const float* __restrict__ bih1, const float* __restrict__ bhh1,
    const float* __restrict__ Wd, const float* __restrict__ bd,
    const float* __restrict__ dpre,
    const float* __restrict__ encq, const float* __restrict__ encout,
    float* __restrict__ h0b, float* __restrict__ h1b, float* __restrict__ ctxb,
    float* __restrict__ qb, float* __restrict__ feat, unsigned* bar)
{
    extern __shared__ char sm[];
    float* wx0 = (float*)sm;                 // each [3][4][512] = 6144 floats
    float* wh0 = wx0 + 6144;
    float* wx1 = wh0 + 6144;
    float* wh1 = wx1 + 6144;
    float* wd  = wh1 + 6144;                 // [4][512]
    float* hs  = wd + 2048;                  // [32][HSW]
    float* qs   = hs + 32*HSW;               // 512
    float* es   = qs + 512;                  // 128
    float* ssum = es + 128;                  // 4

    const int tid = threadIdx.x, w = tid >> 5, lane = tid & 31, row = lane;
    const int blk = blockIdx.x;
    const int j = blk * 4 + w;

    for (int i = tid; i < 6144; i += 128) {
        int g = i / 2048, rem = i - g*2048, ww = rem >> 9, k = rem & 511;
        int r0 = g*Hc + blk*4 + ww;
        wx0[i] = dWih0[(size_t)r0*(Ec + Hc) + Ec + k];
        wh0[i] = dWhh0[(size_t)r0*Hc + k];
        wx1[i] = dWih1[(size_t)r0*Hc + k];
        wh1[i] = dWhh1[(size_t)r0*Hc + k];
    }
    for (int i = tid; i < 2048; i += 128)
        wd[i] = Wd[(size_t)(blk*4 + (i >> 9))*Hc + (i & 511)];
    const float bh0r = bhh0[j], bh0z = bhh0[Hc+j], bh0n = bhh0[2*Hc+j];
    const float bi1r = bih1[j], bi1z = bih1[Hc+j], bi1n = bih1[2*Hc+j];
    const float bh1r = bhh1[j], bh1z = bhh1[Hc+j], bh1n = bhh1[2*Hc+j];
    const float bdj = bd[j];
    __syncthreads();

    unsigned bi = 0;
    for (int t = 0; t < TDc; t++) {
        const int r = t & 1, wix = 1 - r;
        const float* ctxp = ctxb + (size_t)r*Bc*Hc;
        const float* h0p  = h0b  + (size_t)r*Bc*Hc;
        float*       h0n  = h0b  + (size_t)wix*Bc*Hc;
        const float* h1p  = h1b  + (size_t)r*Bc*Hc;
        float*       h1n  = h1b  + (size_t)wix*Bc*Hc;

        // ---- phase 1: cell0 (x=ctx, h=h0) ----
        {
            float air=0.f, aiz=0.f, ain=0.f, ahr=0.f, ahz=0.f, ahn=0.f;
            stage_full(hs, ctxp, 128, tid);
            __syncthreads();
            gate3_full(hs + row*HSW, wx0 + w*512, wx0 + 2048 + w*512, wx0 + 4096 + w*512,
                       air, aiz, ain);
            __syncthreads();
            stage_full(hs, h0p, 128, tid);
            __syncthreads();
            gate3_full(hs + row*HSW, wh0 + w*512, wh0 + 2048 + w*512, wh0 + 4096 + w*512,
                       ahr, ahz, ahn);
            const float* pre = dpre + ((size_t)t*Bc + row)*G3;
            float rg = 1.f / (1.f + __expf(-(air + pre[j]      + ahr + bh0r)));
            float zg = 1.f / (1.f + __expf(-(aiz + pre[Hc+j]   + ahz + bh0z)));
            float ng = tanhf(ain + pre[2*Hc+j] + rg * (ahn + bh0n));
            h0n[(size_t)row*Hc + j] = (1.f - zg)*ng + zg*hs[row*HSW + j];
        }
        gbar(bar, 128u * (++bi));

        // ---- phase 2: cell1 (x=h0n, h=h1) ----
        {
            float air=0.f, aiz=0.f, ain=0.f, ahr=0.f, ahz=0.f, ahn=0.f;
            stage_full(hs, h0n, 128, tid);
            __syncthreads();
            gate3_full(hs + row*HSW, wx1 + w*512, wx1 + 2048 + w*512, wx1 + 4096 + w*512,
                       air, aiz, ain);
            __syncthreads();
            stage_full(hs, h1p, 128, tid);
            __syncthreads();
            gate3_full(hs + row*HSW, wh1 + w*512, wh1 + 2048 + w*512, wh1 + 4096 + w*512,
                       ahr, ahz, ahn);
            float rg = 1.f / (1.f + __expf(-(air + bi1r + ahr + bh1r)));
            float zg = 1.f / (1.f + __expf(-(aiz + bi1z + ahz + bh1z)));
            float ng = tanhf(ain + bi1n + rg * (ahn + bh1n));
            h1n[(size_t)row*Hc + j] = (1.f - zg)*ng + zg*hs[row*HSW + j];
        }
        gbar(bar, 128u * (++bi));

        // ---- phase 3: q = h1n @ Wd^T + bd ----
        {
            stage_full(hs, h1n, 128, tid);
            __syncthreads();
            float acc = 0.f;
            const float* wj = wd + w*512;
            const float* hrow = hs + row*HSW;
            #pragma unroll 8
            for (int k = 0; k < 512; k += 4) {
                float4 hv = *(const float4*)&hrow[k];
                float4 w4 = *(const float4*)&wj[k];
                acc += hv.x*w4.x + hv.y*w4.y + hv.z*w4.z + hv.w*w4.w;
            }
            qb[(size_t)row*Hc + j] = acc + bdj;
        }
        gbar(bar, 128u * (++bi));

        // ---- phase 4: attention + feat (blocks 0..31, b = blk) ----
        if (blk < 32) {
            const int b = blk;
            qs[tid]       = qb[(size_t)b*Hc + tid];
            qs[tid + 128] = qb[(size_t)b*Hc + tid + 128];
            qs[tid + 256] = qb[(size_t)b*Hc + tid + 256];
            qs[tid + 384] = qb[(size_t)b*Hc + tid + 384];
            __syncthreads();
            for (int l = w; l < Lc; l += 4) {
                const float* eqr = encq + ((size_t)l*Bc + b) * Ac;
                float s = 0.f;
                #pragma unroll
                for (int qk = 0; qk < 4; qk++) {
                    int k = qk*128 + lane*4;
                    float4 a = *(const float4*)&eqr[k];
                    float4 c = *(const float4*)&qs[k];
                    s += a.x*c.x + a.y*c.y + a.z*c.z + a.w*c.w;
                }
                #pragma unroll
                for (int off = 16; off; off >>= 1) s += __shfl_xor_sync(0xffffffffu, s, off);
                if (lane == 0) es[l] = __expf(tanhf(s));
            }
            __syncthreads();
            {
                float v = es[tid];
                #pragma unroll
                for (int off = 16; off; off >>= 1) v += __shfl_xor_sync(0xffffffffu, v, off);
                if (lane == 0) ssum[w] = v;
            }
            __syncthreads();
            float inv = 1.f / (ssum[0] + ssum[1] + ssum[2] + ssum[3]);
            float a0=0.f, a1=0.f, a2=0.f, a3=0.f;
            for (int l = 0; l < Lc; l++) {
                float wl = es[l];
                const float* eor = encout + ((size_t)l*Bc + b) * Hc;
                a0 += wl*eor[tid]; a1 += wl*eor[tid+128]; a2 += wl*eor[tid+256]; a3 += wl*eor[tid+384];
            }
            a0 *= inv; a1 *= inv; a2 *= inv; a3 *= inv;
            float* cx = ctxb + (size_t)wix*Bc*Hc + (size_t)b*Hc;
            cx[tid]=a0; cx[tid+128]=a1; cx[tid+256]=a2; cx[tid+384]=a3;
            float* fp = feat + ((size_t)t*Bc + b) * 2*Hc;
            const float* h1r = h1n + (size_t)b*Hc;
            fp[tid]=h1r[tid]; fp[tid+128]=h1r[tid+128]; fp[tid+256]=h1r[tid+256]; fp[tid+384]=h1r[tid+384];
            fp[Hc+tid]=a0; fp[Hc+tid+128]=a1; fp[Hc+tid+256]=a2; fp[Hc+tid+384]=a3;
            __syncthreads();
        }
        ++bi;
        if (t < TDc - 1) gbar(bar, 128u * bi);
    }
}

// ================================================================================
extern "C" void kernel_launch(void* const* d_in, const int* in_sizes, int n_in,
                              void* d_out, int out_size)
{
    const int*   src_tokens = (const int*)  d_in[0];
    const int*   trgt_seq   = (const int*)  d_in[1];
    const float* enc_embed  = (const float*)d_in[3];
    const float* enc_Wih0   = (const float*)d_in[4];
    const float* enc_Whh0   = (const float*)d_in[5];
    const float* enc_bih0   = (const float*)d_in[6];
    const float* enc_bhh0   = (const float*)d_in[7];
    const float* enc_Wih1   = (const float*)d_in[8];
    const float* enc_Whh1   = (const float*)d_in[9];
    const float* enc_bih1   = (const float*)d_in[10];
    const float* enc_bhh1   = (const float*)d_in[11];
    const float* dec_embed  = (const float*)d_in[12];
    const float* dec_Wih0   = (const float*)d_in[13];
    const float* dec_Whh0   = (const float*)d_in[14];
    const float* dec_bih0   = (const float*)d_in[15];
    const float* dec_bhh0   = (const float*)d_in[16];
    const float* dec_Wih1   = (const float*)d_in[17];
    const float* dec_Whh1   = (const float*)d_in[18];
    const float* dec_bih1   = (const float*)d_in[19];
    const float* dec_bhh1   = (const float*)d_in[20];
    const float* attn_We    = (const float*)d_in[21];
    const float* attn_be    = (const float*)d_in[22];
    const float* attn_Wd    = (const float*)d_in[23];
    const float* attn_bd    = (const float*)d_in[24];
    const float* mlp_W1     = (const float*)d_in[25];
    const float* mlp_b1     = (const float*)d_in[26];
    const float* mlp_W2     = (const float*)d_in[27];
    const float* mlp_b2     = (const float*)d_in[28];

    float *emb, *decemb, *gi, *y0, *y1, *eo, *eq, *dpre, *h0b, *h1b, *ctxb, *qb, *feat;
    unsigned* bars;
    __nv_bfloat16 *Ah, *Al, *Wh, *Wl, *Bh, *Bl;
    cudaGetSymbolAddress((void**)&emb,    d_emb);
    cudaGetSymbolAddress((void**)&decemb, d_decemb);
    cudaGetSymbolAddress((void**)&gi,     d_gi);
    cudaGetSymbolAddress((void**)&y0,     d_y0);
    cudaGetSymbolAddress((void**)&y1,     d_y1);
    cudaGetSymbolAddress((void**)&eo,     d_eo);
    cudaGetSymbolAddress((void**)&eq,     d_eq);
    cudaGetSymbolAddress((void**)&dpre,   d_dpre);
    cudaGetSymbolAddress((void**)&h0b,    d_h0b);
    cudaGetSymbolAddress((void**)&h1b,    d_h1b);
    cudaGetSymbolAddress((void**)&ctxb,   d_ctxb);
    cudaGetSymbolAddress((void**)&qb,     d_qb);
    cudaGetSymbolAddress((void**)&feat,   d_feat);
    cudaGetSymbolAddress((void**)&bars,   d_bars);
    cudaGetSymbolAddress((void**)&Ah,     d_Ah);
    cudaGetSymbolAddress((void**)&Al,     d_Al);
    cudaGetSymbolAddress((void**)&Wh,     d_Wh);
    cudaGetSymbolAddress((void**)&Wl,     d_Wl);
    cudaGetSymbolAddress((void**)&Bh,     d_Bh);
    cudaGetSymbolAddress((void**)&Bl,     d_Bl);

    cudaFuncSetAttribute(gemm_bf16,       cudaFuncAttributeMaxDynamicSharedMemorySize, GEMM_SMEM);
    cudaFuncSetAttribute(gemm_bf16_w256,  cudaFuncAttributeMaxDynamicSharedMemorySize, GEMM2_SMEM);
    cudaFuncSetAttribute(enc_gru_persist, cudaFuncAttributeMaxDynamicSharedMemorySize, ENC_SMEM);
    cudaFuncSetAttribute(dec_persist,     cudaFuncAttributeMaxDynamicSharedMemorySize, DEC_SMEM);

    cudaMemsetAsync(bars, 0, 8*sizeof(unsigned));
    cudaMemsetAsync(h0b,  0, Bc*Hc*sizeof(float));
    cudaMemsetAsync(h1b,  0, Bc*Hc*sizeof(float));
    cudaMemsetAsync(ctxb, 0, Bc*Hc*sizeof(float));

    // embeddings
    gather_rows<<<Lc*Bc, 128>>>(src_tokens, enc_embed, emb, 0);
    gather_rows<<<MBc,   128>>>(trgt_seq,   dec_embed, decemb, 1);

    // mlp_W2 conversion
    { long n = (long)Vc * 1024; conv_split4<<<(unsigned)(n/1024), 256>>>(mlp_W2, Bh, Bl, n, n); }

    // ===== encoder layer0 pre + persistent recurrence (per-dir barriers: bars 0,1) =====
    { long n = (long)Lc*Bc*Ec;  conv_split4<<<(unsigned)(n/1024), 256>>>(emb, Ah, Al, n, n); }
    { long n = (long)2*G3*Ec;   conv_split4<<<(unsigned)(n/1024), 256>>>(enc_Wih0, Wh, Wl, n, n); }
    gemm_bf16<<<dim3(2*G3/128, Lc*Bc/128), 256, GEMM_SMEM>>>(
        Ec, Ah, Al, Wh, Wl, enc_bih0, gi, nullptr, nullptr, 2*G3, 0);
    enc_gru_persist<<<128, 256, ENC_SMEM>>>(gi, enc_Whh0, enc_bhh0, y0, bars + 0);

    // ===== encoder layer1 (bars 2,3) =====
    { long n = (long)Lc*Bc*2*Hc; conv_split4<<<(unsigned)(n/1024), 256>>>(y0, Ah, Al, n, n); }
    { long n = (long)2*G3*2*Hc;  conv_split4<<<(unsigned)(n/1024), 256>>>(enc_Wih1, Wh, Wl, n, n); }
    gemm_bf16<<<dim3(2*G3/128, Lc*Bc/128), 256, GEMM_SMEM>>>(
        2*Hc, Ah, Al, Wh, Wl, enc_bih1, gi, nullptr, nullptr, 2*G3, 0);
    enc_gru_persist<<<128, 256, ENC_SMEM>>>(gi, enc_Whh1, enc_bhh1, y1, bars + 2);

    combine_enc<<<Lc*Bc, 128>>>(y1, eo);

    // ===== enc_q =====
    { long n = (long)Lc*Bc*Hc; conv_split4<<<(unsigned)(n/1024), 256>>>(eo, Ah, Al, n, n); }
    { long n = (long)Ac*Hc;    conv_split4<<<(unsigned)(n/1024), 256>>>(attn_We, Wh, Wl, n, n); }
    gemm_bf16<<<dim3(Ac/128, Lc*Bc/128), 256, GEMM_SMEM>>>(
        Hc, Ah, Al, Wh, Wl, attn_be, eq, nullptr, nullptr, Ac, 0);

    // ===== decoder pre =====
    { long nv = (long)MBc*Ec, nt = (long)MPAD*Ec;
      conv_split4<<<(unsigned)(nt/1024), 256>>>(decemb, Ah, Al, nv, nt); }
    { long n = (long)G3*Ec;
      conv_split2d4<<<(unsigned)(n/1024), 256>>>(dec_Wih0, Ec + Hc, G3, Ec, Wh, Wl); }
    gemm_bf16<<<dim3(G3/128, MPAD/128), 256, GEMM_SMEM>>>(
        Ec, Ah, Al, Wh, Wl, dec_bih0, dpre, nullptr, nullptr, G3, 0);

    // ===== persistent decoder (bars 4) =====
    dec_persist<<<128, 128, DEC_SMEM>>>(
        dec_Wih0, dec_Whh0, dec_bhh0,
        dec_Wih1, dec_Whh1, dec_bih1, dec_bhh1,
        attn_Wd, attn_bd, dpre, eq, eo,
        h0b, h1b, ctxb, qb, feat, bars + 4);

    // ===== MLP1 (split-bf16 out) =====
    { long nv = (long)MBc*2*Hc, nt = (long)MPAD*2*Hc;
      conv_split4<<<(unsigned)(nt/1024), 256>>>(feat, Ah, Al, nv, nt); }
    { long n = (long)2*Hc*2*Hc; conv_split4<<<(unsigned)(n/1024), 256>>>(mlp_W1, Wh, Wl, n, n); }
    __nv_bfloat16* Ah2 = Ah + (size_t)MPAD * 1024;
    __nv_bfloat16* Al2 = Al + (size_t)MPAD * 1024;
    gemm_bf16<<<dim3(2*Hc/128, MPAD/128), 256, GEMM_SMEM>>>(
        2*Hc, Ah, Al, Wh, Wl, mlp_b1, nullptr, Ah2, Al2, 2*Hc, F_RELU | F_SPLIT);

    // ===== MLP2 logits: 128x256 tiles =====
    gemm_bf16_w256<<<dim3(Vc/256, MPAD/128), 512, GEMM2_SMEM>>>(
        2*Hc, Ah2, Al2, Bh, Bl, mlp_b2, (float*)d_out, Vc);
}